// round 8
// baseline (speedup 1.0000x reference)
#include <cuda_runtime.h>
#include <cuda_fp16.h>
#include <math.h>
#include <stdint.h>

// Problem constants
#define NB 2
#define NC 128
#define FH 80
#define FW 80
#define HS 40            // downsampled H=W
#define NQ 1600          // HS*HS
#define NEPS 0.1152f     // 1152 * EPS
#define SCL 10.0f
#define MROWS 2048       // NC * 16 offsets

// fp16 mma GEMM2 config
#define KT 32
#define G2_SMEM 32768

// fuse2 column-loop config
#define F2_QCH 32        // q chunks, each 1600/32 = 50 rows

// Static scratch
__device__ float  g_ds[NB*3*NC*NQ];
__device__ float  g_E[NB*2*NQ];
__device__ float  g_ninv[NB*2*NQ];
__device__ float  g_smax[NB*2*NQ];           // per-column max (atomicMax)
__device__ float  g_ssum[NB*2*NQ];           // per-column sum of exp (atomicAdd)
__device__ float  g_sinv[NB*2*NQ];           // 1/ssum
__device__ float  g_bufA[NB*2*NQ*NQ];        // pixcorr / final fused scores
__device__ float  g_bufB[NB*2*NQ*NQ];        // post-psfuse scores
__device__ __align__(16) __half g_Gh[NB*2*MROWS*NQ];
__device__ __align__(16) __half g_ATh[NB*2*NQ*NQ];   // UNNORMALIZED exp, transposed
__device__ float  g_T[NB*2*MROWS*NQ];

__device__ __forceinline__ void atomicMaxF(float* a, float v) {
    if (v >= 0.f) atomicMax((int*)a, __float_as_int(v));
    else          atomicMin((unsigned int*)a, __float_as_uint(v));
}

// ---------------------------------------------------------------- downsample
__global__ void k_downsample(const float* __restrict__ left,
                             const float* __restrict__ right,
                             const float* __restrict__ mid) {
    int idx = blockIdx.x * blockDim.x + threadIdx.x;
    const int total = NB*3*NC*NQ;
    if (idx >= total) return;
    int q = idx % NQ;
    int t = idx / NQ;
    int c = t % NC; t /= NC;
    int img = t % 3; int b = t / 3;
    const float* src = (img == 0) ? left : (img == 1 ? right : mid);
    int qh = q / HS, qw = q % HS;
    g_ds[idx] = src[(size_t)((b*NC + c)*FH + 2*qh)*FW + 2*qw];
}

// ------------------------------------------------- channel sum-of-squares
__global__ void k_sumsq() {
    int idx = blockIdx.x*blockDim.x + threadIdx.x;
    const int total = NB*2*NQ;
    if (idx >= total) return;
    int q = idx % NQ; int t = idx / NQ;
    int s = t % 2; int b = t / 2;
    const float* p = g_ds + (size_t)(b*3 + s)*NC*NQ + q;
    float acc = 0.f;
    #pragma unroll 8
    for (int c = 0; c < NC; ++c) { float v = p[(size_t)c*NQ]; acc += v*v; }
    g_E[idx] = acc;
}

// -------------------------------------------------- patch norm + stats init
__global__ void k_norm() {
    int idx = blockIdx.x*blockDim.x + threadIdx.x;
    const int total = NB*2*NQ;
    if (idx >= total) return;
    int q = idx % NQ; int bs = idx / NQ;
    int qh = q/HS, qw = q%HS;
    float acc = NEPS;
    for (int di=-1; di<=1; ++di) {
        int h = qh+di; if (h < 0 || h >= HS) continue;
        for (int dj=-1; dj<=1; ++dj) {
            int w = qw+dj; if (w < 0 || w >= HS) continue;
            acc += g_E[bs*NQ + h*HS + w];
        }
    }
    g_ninv[idx] = rsqrtf(acc);
    g_smax[idx] = -3.4e38f;     // init softmax stats (fresh every replay)
    g_ssum[idx] = 0.f;
}

// ----------------------------- GEMM1 (fp32): PixCorr[q,p] = sum_c L[c,q]*M[c,p]
__global__ void k_gemm1() {
    int bs = blockIdx.z;
    int b = bs >> 1, s = bs & 1;
    const float* A  = g_ds + (size_t)(b*3 + s)*NC*NQ;
    const float* Bm = g_ds + (size_t)(b*3 + 2)*NC*NQ;
    float* Cout = g_bufA + (size_t)bs*NQ*NQ;
    __shared__ float As[16][64];
    __shared__ float Bs[16][64];
    int tx = threadIdx.x;
    int m0 = blockIdx.x*64, n0 = blockIdx.y*64;
    int lk = tx >> 4, lm = (tx & 15) * 4;
    int lr = tx >> 4, lc = tx & 15;
    float acc[4][4];
    #pragma unroll
    for (int i=0;i<4;i++)
        #pragma unroll
        for (int j=0;j<4;j++) acc[i][j] = 0.f;
    for (int k0 = 0; k0 < NC; k0 += 16) {
        *(float4*)&As[lk][lm] = *(const float4*)&A [(size_t)(k0+lk)*NQ + m0 + lm];
        *(float4*)&Bs[lk][lm] = *(const float4*)&Bm[(size_t)(k0+lk)*NQ + n0 + lm];
        __syncthreads();
        #pragma unroll
        for (int kk = 0; kk < 16; ++kk) {
            float4 av = *(const float4*)&As[kk][lr*4];
            float4 bv = *(const float4*)&Bs[kk][lc*4];
            float a[4] = {av.x, av.y, av.z, av.w};
            float bb[4] = {bv.x, bv.y, bv.z, bv.w};
            #pragma unroll
            for (int i=0;i<4;i++)
                #pragma unroll
                for (int j=0;j<4;j++) acc[i][j] += a[i]*bb[j];
        }
        __syncthreads();
    }
    #pragma unroll
    for (int i=0;i<4;i++) {
        float4 v = make_float4(acc[i][0],acc[i][1],acc[i][2],acc[i][3]);
        *(float4*)&Cout[(size_t)(m0+lr*4+i)*NQ + n0 + lc*4] = v;
    }
}

// -------- FUSED patchsum + fuse1, 4 outputs per thread (bufA -> bufB)
__global__ void k_psfuse() {
    int idx = blockIdx.x*blockDim.x + threadIdx.x;
    const int total4 = NB*2*NQ*(NQ/4);
    if (idx >= total4) return;
    int p4 = (idx % (NQ/4)) * 4;
    int t = idx / (NQ/4);
    int q = t % NQ;
    int bs = t / NQ;
    const float* __restrict__ Cm = g_bufA + (size_t)bs*NQ*NQ;
    const float* __restrict__ ninv = g_ninv + bs*NQ;
    const int qh = q/HS, qw = q - (q/HS)*HS;
    const int ph0 = p4/HS, pw0 = p4 - (p4/HS)*HS;
    float acc[4] = {0.f,0.f,0.f,0.f};

    #pragma unroll
    for (int ei = 0; ei < 3; ++ei) {
        const int e = (ei==0) ? 0 : (ei==1 ? -1 : 1);
        const int Q = q + e;
        if (Q < 0 || Q >= NQ) continue;
        int Qh = qh, Qw = qw + e;
        if (Qw < 0) { Qh -= 1; Qw = HS-1; }
        else if (Qw >= HS) { Qh += 1; Qw = 0; }
        const float nv = ninv[Q];
        int Pj[4], Phj[4], Pwj[4]; bool Vj[4];
        #pragma unroll
        for (int j = 0; j < 4; ++j) {
            int P = p4 + e + j;
            int Pw = pw0 + e + j, Ph = ph0;
            if (Pw < 0) { Ph -= 1; Pw = HS-1; }
            else if (Pw >= HS) { Ph += 1; Pw = 0; }
            Pj[j] = P; Phj[j] = Ph; Pwj[j] = Pw;
            Vj[j] = (P >= 0) && (P < NQ);
        }
        float ps[4] = {0.f,0.f,0.f,0.f};
        #pragma unroll
        for (int di = -1; di <= 1; ++di) {
            int Qhd = Qh + di;
            if (Qhd < 0 || Qhd >= HS) continue;
            #pragma unroll
            for (int dj = -1; dj <= 1; ++dj) {
                int Qwd = Qw + dj;
                if (Qwd < 0 || Qwd >= HS) continue;
                int sh = di*HS + dj;
                const float* row = Cm + (size_t)(Q + sh)*NQ;
                #pragma unroll
                for (int j = 0; j < 4; ++j) {
                    int Phd = Phj[j] + di, Pwd = Pwj[j] + dj;
                    if (Vj[j] && Phd >= 0 && Phd < HS && Pwd >= 0 && Pwd < HS)
                        ps[j] += row[Pj[j] + sh];
                }
            }
        }
        #pragma unroll
        for (int j = 0; j < 4; ++j) acc[j] += ps[j] * nv;
    }
    *(float4*)&g_bufB[((size_t)(bs*NQ + q))*NQ + p4] =
        make_float4(acc[0], acc[1], acc[2], acc[3]);
}

// ---------------- fuse pass 2, column-loop (bufB -> bufA) + per-column max
// Thread owns 4 columns (p4) and 50 q-rows. Tap column bases fixed per thread.
__global__ void k_fuse2() {
    int idx = blockIdx.x*blockDim.x + threadIdx.x;
    const int total = NB*2*(NQ/4)*F2_QCH;        // 4*400*32 = 51200
    if (idx >= total) return;
    const int pg = idx % (NQ/4);
    const int tq = (idx / (NQ/4)) % F2_QCH;
    const int bs = idx / ((NQ/4)*F2_QCH);
    const int p4 = pg * 4;
    const float* __restrict__ F = g_bufB + (size_t)bs*NQ*NQ;
    float* __restrict__ O = g_bufA + (size_t)bs*NQ*NQ;
    const int ph = p4/HS, pw0 = p4 - (p4/HS)*HS;
    const bool pmA = (ph > 0);        // aligned path for minus tap
    const bool ppA = (ph < HS-1);     // aligned path for plus tap
    const int pmb = pmA ? (p4 - HS) : ((HS-1)*HS + pw0 - 1);
    const int ppb = ppA ? (p4 + HS) : (pw0 + 1);

    float mx0 = -3.4e38f, mx1 = -3.4e38f, mx2 = -3.4e38f, mx3 = -3.4e38f;
    const int q0 = tq * (NQ/F2_QCH), q1 = q0 + (NQ/F2_QCH);
    int qh = q0/HS, qw = q0 - (q0/HS)*HS;
    for (int q = q0; q < q1; ++q) {
        float4 v = *(const float4*)&F[(size_t)q*NQ + p4];
        float a0 = v.x, a1 = v.y, a2 = v.z, a3 = v.w;
        if (q > 0) {
            const int qm = (qh > 0) ? (q - HS) : ((HS-1)*HS + qw - 1);
            const float* rm = F + (size_t)qm*NQ;
            if (pmA) {
                float4 u = *(const float4*)&rm[pmb];
                a0 += u.x; a1 += u.y; a2 += u.z; a3 += u.w;
            } else {
                if (p4 + 0 > 0) a0 += rm[pmb + 0];
                a1 += rm[pmb + 1];
                a2 += rm[pmb + 2];
                a3 += rm[pmb + 3];
            }
        }
        if (q < NQ-1) {
            const int qp = (qh < HS-1) ? (q + HS) : (qw + 1);
            const float* rp = F + (size_t)qp*NQ;
            if (ppA) {
                float4 u = *(const float4*)&rp[ppb];
                a0 += u.x; a1 += u.y; a2 += u.z; a3 += u.w;
            } else {
                a0 += rp[ppb + 0];
                a1 += rp[ppb + 1];
                a2 += rp[ppb + 2];
                if (p4 + 3 < NQ-1) a3 += rp[ppb + 3];
            }
        }
        *(float4*)&O[(size_t)q*NQ + p4] = make_float4(a0, a1, a2, a3);
        mx0 = fmaxf(mx0, a0); mx1 = fmaxf(mx1, a1);
        mx2 = fmaxf(mx2, a2); mx3 = fmaxf(mx3, a3);
        qw += 1; if (qw == HS) { qw = 0; qh += 1; }
    }
    float* sm = g_smax + bs*NQ + p4;
    atomicMaxF(sm + 0, mx0);
    atomicMaxF(sm + 1, mx1);
    atomicMaxF(sm + 2, mx2);
    atomicMaxF(sm + 3, mx3);
}

// --------------- attnT: UNNORMALIZED exp, transposed half; column-sum atomics
__global__ void k_attnT() {
    __shared__ float tile[32][33];
    int bs = blockIdx.z;
    int q0 = blockIdx.x * 32, p0 = blockIdx.y * 32;
    const float* __restrict__ F = g_bufA + (size_t)bs*NQ*NQ;
    __half* __restrict__ O = g_ATh + (size_t)bs*NQ*NQ;
    int tx = threadIdx.x, ty = threadIdx.y;  // 32 x 8
    for (int r = ty; r < 32; r += 8)
        tile[r][tx] = F[(size_t)(q0+r)*NQ + p0 + tx];
    __syncthreads();
    for (int r = ty; r < 32; r += 8) {
        int p = p0 + r;
        float e = __expf(SCL * (tile[tx][r] - g_smax[bs*NQ + p]));
        O[(size_t)p*NQ + q0 + tx] = __float2half_rn(e);
        // warp-reduce sum over the 32 q values (lanes)
        #pragma unroll
        for (int off = 16; off > 0; off >>= 1)
            e += __shfl_xor_sync(0xffffffffu, e, off);
        if (tx == 0) atomicAdd(&g_ssum[bs*NQ + p], e);
    }
}

// --------------- tiny: sinv = 1/ssum
__global__ void k_sinv() {
    int idx = blockIdx.x*blockDim.x + threadIdx.x;
    if (idx < NB*2*NQ) g_sinv[idx] = 1.0f / g_ssum[idx];
}

// --------------- build paste operand G[bs][m][q] as half, 8 q per thread
__global__ void k_buildG(const float* __restrict__ raw_left,
                         const float* __restrict__ raw_right) {
    int idx = blockIdx.x*blockDim.x + threadIdx.x;
    const int total8 = NB*2*MROWS*(NQ/8);
    if (idx >= total8) return;
    int q8 = (idx % (NQ/8)) * 8;
    int t = idx / (NQ/8);
    int m = t % MROWS;
    int bs = t / MROWS;
    int b = bs >> 1, s = bs & 1;
    int c = m >> 4;
    int o = m & 15;
    int dy = (o >> 2) - 1, dx = (o & 3) - 1;
    int qh = q8 / HS, qw0 = q8 - (q8/HS)*HS;
    int y = 2*qh + dy;
    const float* raw = (s ? raw_right : raw_left) + (size_t)(b*NC + c)*FH*FW;
    __half hv[8];
    if (y >= 0 && y < FH) {
        const float* rrow = raw + (size_t)y*FW;
        #pragma unroll
        for (int j = 0; j < 8; ++j) {
            int x = 2*(qw0 + j) + dx;
            hv[j] = (x >= 0 && x < FW) ? __float2half_rn(rrow[x]) : __half(0.f);
        }
    } else {
        #pragma unroll
        for (int j = 0; j < 8; ++j) hv[j] = __half(0.f);
    }
    *(uint4*)&g_Gh[(size_t)(bs*MROWS + m)*NQ + q8] = *(uint4*)hv;
}

// ------------- GEMM2 (mma.sync fp16, f32 accum): T[m,p] = sum_q G[m,q] * attnT[p,q]
__device__ __forceinline__ void mma_f16(float* c, uint32_t a0, uint32_t a1,
                                        uint32_t a2, uint32_t a3,
                                        uint32_t b0, uint32_t b1) {
    asm volatile(
        "mma.sync.aligned.m16n8k16.row.col.f32.f16.f16.f32 "
        "{%0,%1,%2,%3}, {%4,%5,%6,%7}, {%8,%9}, {%0,%1,%2,%3};"
        : "+f"(c[0]), "+f"(c[1]), "+f"(c[2]), "+f"(c[3])
        : "r"(a0), "r"(a1), "r"(a2), "r"(a3), "r"(b0), "r"(b1));
}

__global__ void __launch_bounds__(256) k_gemm2h() {
    extern __shared__ char smx[];
    const int bs = blockIdx.z;
    const __half* __restrict__ Gm = g_Gh  + (size_t)bs*MROWS*NQ;
    const __half* __restrict__ Bm = g_ATh + (size_t)bs*NQ*NQ;
    float* __restrict__ Tm = g_T + (size_t)bs*MROWS*NQ;
    const int m0 = blockIdx.x * 128, n0 = blockIdx.y * 128;
    const int t = threadIdx.x;
    const int lane = t & 31, wid = t >> 5;
    const int wm = wid & 1, wn = wid >> 1;

    const int prow = t >> 1, ps = t & 1;
    const int pmt = prow >> 4, prr = prow & 15;
    const int pgA = prr & 7;
    const int hwA = (prr >> 3) << 3;
    const int pnt = prow >> 3, pgB = prow & 7;
    const bool pBvalid = (n0 + prow) < NQ;

    uint32_t al[4], ah[4], bl[4], bh[4];

    float acc[4][4][4];
    #pragma unroll
    for (int i=0;i<4;i++)
        #pragma unroll
        for (int j=0;j<4;j++)
            #pragma unroll
            for (int k=0;k<4;k++) acc[i][j][k] = 0.f;

    {
        const uint4* pa = (const uint4*)(Gm + (size_t)(m0+prow)*NQ + ps*16);
        uint4 lo = pa[0], hi = pa[1];
        al[0]=lo.x; al[1]=lo.y; al[2]=lo.z; al[3]=lo.w;
        ah[0]=hi.x; ah[1]=hi.y; ah[2]=hi.z; ah[3]=hi.w;
        if (pBvalid) {
            const uint4* pb = (const uint4*)(Bm + (size_t)(n0+prow)*NQ + ps*16);
            uint4 blo = pb[0], bhi = pb[1];
            bl[0]=blo.x; bl[1]=blo.y; bl[2]=blo.z; bl[3]=blo.w;
            bh[0]=bhi.x; bh[1]=bhi.y; bh[2]=bhi.z; bh[3]=bhi.w;
        } else {
            #pragma unroll
            for (int j=0;j<4;j++) { bl[j]=0u; bh[j]=0u; }
        }
    }

    const int NTILES = NQ / KT;
    for (int it = 0; it < NTILES; ++it) {
        char* base = smx + (it & 1) * 16384;
        char* Asl = base;
        char* Bsl = base + 8192;

        {
            char* aw = Asl + ((ps*8 + pmt)*32 + pgA*4) * 16 + hwA;
            char* bw = Bsl + ((ps*16 + pnt)*32 + pgB*4) * 8;
            #pragma unroll
            for (int j = 0; j < 4; ++j) {
                *(uint2*)(aw + j*16) = make_uint2(al[j], ah[j]);
                *(uint2*)(bw + j*8)  = make_uint2(bl[j], bh[j]);
            }
        }
        __syncthreads();

        if (it + 1 < NTILES) {
            int k0n = (it + 1) * KT;
            const uint4* pa = (const uint4*)(Gm + (size_t)(m0+prow)*NQ + k0n + ps*16);
            uint4 lo = pa[0], hi = pa[1];
            al[0]=lo.x; al[1]=lo.y; al[2]=lo.z; al[3]=lo.w;
            ah[0]=hi.x; ah[1]=hi.y; ah[2]=hi.z; ah[3]=hi.w;
            if (pBvalid) {
                const uint4* pb = (const uint4*)(Bm + (size_t)(n0+prow)*NQ + k0n + ps*16);
                uint4 blo = pb[0], bhi = pb[1];
                bl[0]=blo.x; bl[1]=blo.y; bl[2]=blo.z; bl[3]=blo.w;
                bh[0]=bhi.x; bh[1]=bhi.y; bh[2]=bhi.z; bh[3]=bhi.w;
            }
        }

        #pragma unroll
        for (int s = 0; s < 2; ++s) {
            uint4 af[4]; uint2 bf[4];
            #pragma unroll
            for (int mt = 0; mt < 4; ++mt)
                af[mt] = *(const uint4*)(Asl + (((s*8 + wm*4 + mt)*32 + lane) * 16));
            #pragma unroll
            for (int nt = 0; nt < 4; ++nt)
                bf[nt] = *(const uint2*)(Bsl + (((s*16 + wn*4 + nt)*32 + lane) * 8));
            #pragma unroll
            for (int mt = 0; mt < 4; ++mt)
                #pragma unroll
                for (int nt = 0; nt < 4; ++nt)
                    mma_f16(acc[mt][nt], af[mt].x, af[mt].z, af[mt].y, af[mt].w,
                            bf[nt].x, bf[nt].y);
        }
    }

    #pragma unroll
    for (int mt = 0; mt < 4; ++mt) {
        int m = m0 + wm*64 + mt*16 + (lane >> 2);
        #pragma unroll
        for (int nt = 0; nt < 4; ++nt) {
            int n = n0 + wn*32 + nt*8 + 2*(lane & 3);
            if (n < NQ) {
                *(float2*)&Tm[(size_t)m*NQ + n]     = make_float2(acc[mt][nt][0], acc[mt][nt][1]);
                *(float2*)&Tm[(size_t)(m+8)*NQ + n] = make_float2(acc[mt][nt][2], acc[mt][nt][3]);
            }
        }
    }
}

// ------------- gather epilogue + sinv normalization + cosine-window blend
__global__ void k_combine(float* __restrict__ out) {
    int idx = blockIdx.x*blockDim.x + threadIdx.x;
    const int total = NB*NC*FH*FW;
    if (idx >= total) return;
    int X = idx % FW; int t = idx / FW;
    int Y = t % FH; t /= FH;
    int c = t % NC; int b = t / NC;

    int dys[2], hh[2]; int ny = 0;
    if ((Y & 1) == 0) {
        dys[ny] = 0; hh[ny] = Y >> 1; ny++;
        if (Y >= 2) { dys[ny] = 2; hh[ny] = (Y-2) >> 1; ny++; }
    } else {
        dys[ny] = 1; hh[ny] = (Y-1) >> 1; ny++;
        if (Y <= 2*HS - 3) { dys[ny] = -1; hh[ny] = (Y+1) >> 1; ny++; }
    }
    int dxs[2], ww[2]; int nx = 0;
    if ((X & 1) == 0) {
        dxs[nx] = 0; ww[nx] = X >> 1; nx++;
        if (X >= 2) { dxs[nx] = 2; ww[nx] = (X-2) >> 1; nx++; }
    } else {
        dxs[nx] = 1; ww[nx] = (X-1) >> 1; nx++;
        if (X <= 2*HS - 3) { dxs[nx] = -1; ww[nx] = (X+1) >> 1; nx++; }
    }

    const float PI = 3.14159265358979323846f;
    float wl = 0.5f*(1.f + cosf(PI * (float)X        / (float)(FW-1)));
    float wr = 0.5f*(1.f + cosf(PI * (float)(FW-1-X) / (float)(FW-1)));

    float res = 0.f;
    for (int s = 0; s < 2; ++s) {
        int bs = b*2 + s;
        const float* T = g_T + (size_t)bs*MROWS*NQ;
        const float* sv = g_sinv + bs*NQ;
        float acc = 0.f;
        for (int iy = 0; iy < ny; ++iy) {
            for (int ix = 0; ix < nx; ++ix) {
                int m = c*16 + (dys[iy]+1)*4 + (dxs[ix]+1);
                int pq = hh[iy]*HS + ww[ix];
                acc += T[(size_t)m*NQ + pq] * sv[pq];
            }
        }
        res += (s == 0 ? wl : wr) * 0.25f * acc;
    }
    out[idx] = res;
}

// ------------------------------------------------------------------ launcher
extern "C" void kernel_launch(void* const* d_in, const int* in_sizes, int n_in,
                              void* d_out, int out_size) {
    const float* left      = (const float*)d_in[0];
    const float* right     = (const float*)d_in[1];
    const float* mid       = (const float*)d_in[2];
    const float* raw_left  = (const float*)d_in[3];
    const float* raw_right = (const float*)d_in[4];
    float* outp = (float*)d_out;

    cudaFuncSetAttribute(k_gemm2h, cudaFuncAttributeMaxDynamicSharedMemorySize, G2_SMEM);

    int t1 = NB*3*NC*NQ;
    k_downsample<<<(t1+255)/256, 256>>>(left, right, mid);
    int t2 = NB*2*NQ;
    k_sumsq<<<(t2+127)/128, 128>>>();
    k_norm<<<(t2+127)/128, 128>>>();         // also inits smax/ssum

    dim3 g1(NQ/64, NQ/64, NB*2);
    k_gemm1<<<g1, 256>>>();

    int tp4 = NB*2*NQ*(NQ/4);
    k_psfuse<<<(tp4+255)/256, 256>>>();

    int tf2 = NB*2*(NQ/4)*F2_QCH;
    k_fuse2<<<(tf2+255)/256, 256>>>();       // scores + column max

    k_attnT<<<dim3(NQ/32, NQ/32, NB*2), dim3(32, 8)>>>();  // exp + column sums
    k_sinv<<<(t2+255)/256, 256>>>();

    int tg8 = NB*2*MROWS*(NQ/8);
    k_buildG<<<(tg8+255)/256, 256>>>(raw_left, raw_right);

    dim3 g2(MROWS/128, (NQ+127)/128, NB*2);
    k_gemm2h<<<g2, 256, G2_SMEM>>>();

    int to = NB*NC*FH*FW;
    k_combine<<<(to+255)/256, 256>>>(outp);
}

// round 9
// speedup vs baseline: 1.0885x; 1.0885x over previous
#include <cuda_runtime.h>
#include <cuda_fp16.h>
#include <math.h>
#include <stdint.h>

// Problem constants
#define NB 2
#define NC 128
#define FH 80
#define FW 80
#define HS 40            // downsampled H=W
#define NQ 1600          // HS*HS
#define NEPS 0.1152f     // 1152 * EPS
#define SCL 10.0f
#define MROWS 2048       // NC * 16 offsets

// fp16 mma GEMM2 config
#define KT 32
#define G2_SMEM 32768

// Static scratch
__device__ float  g_ds[NB*3*NC*NQ];
__device__ float  g_E[NB*2*NQ];
__device__ float  g_ninv[NB*2*NQ];
__device__ float  g_smax[NB*2*NQ];
__device__ float  g_sinv[NB*2*NQ];
__device__ float  g_bufA[NB*2*NQ*NQ];        // ping
__device__ float  g_bufB[NB*2*NQ*NQ];        // pong
__device__ __align__(16) __half g_Gh[NB*2*MROWS*NQ];
__device__ __align__(16) __half g_ATh[NB*2*NQ*NQ];
__device__ float  g_T[NB*2*MROWS*NQ];

// ---------------------------------------------------------------- downsample
__global__ void k_downsample(const float* __restrict__ left,
                             const float* __restrict__ right,
                             const float* __restrict__ mid) {
    int idx = blockIdx.x * blockDim.x + threadIdx.x;
    const int total = NB*3*NC*NQ;
    if (idx >= total) return;
    int q = idx % NQ;
    int t = idx / NQ;
    int c = t % NC; t /= NC;
    int img = t % 3; int b = t / 3;
    const float* src = (img == 0) ? left : (img == 1 ? right : mid);
    int qh = q / HS, qw = q % HS;
    g_ds[idx] = src[(size_t)((b*NC + c)*FH + 2*qh)*FW + 2*qw];
}

// ------------------------------------------------- channel sum-of-squares
__global__ void k_sumsq() {
    int idx = blockIdx.x*blockDim.x + threadIdx.x;
    const int total = NB*2*NQ;
    if (idx >= total) return;
    int q = idx % NQ; int t = idx / NQ;
    int s = t % 2; int b = t / 2;
    const float* p = g_ds + (size_t)(b*3 + s)*NC*NQ + q;
    float acc = 0.f;
    #pragma unroll 8
    for (int c = 0; c < NC; ++c) { float v = p[(size_t)c*NQ]; acc += v*v; }
    g_E[idx] = acc;
}

// -------------------------------------------------- patch norm
__global__ void k_norm() {
    int idx = blockIdx.x*blockDim.x + threadIdx.x;
    const int total = NB*2*NQ;
    if (idx >= total) return;
    int q = idx % NQ; int bs = idx / NQ;
    int qh = q/HS, qw = q%HS;
    float acc = NEPS;
    for (int di=-1; di<=1; ++di) {
        int h = qh+di; if (h < 0 || h >= HS) continue;
        for (int dj=-1; dj<=1; ++dj) {
            int w = qw+dj; if (w < 0 || w >= HS) continue;
            acc += g_E[bs*NQ + h*HS + w];
        }
    }
    g_ninv[idx] = rsqrtf(acc);
}

// ----------------------------- GEMM1 (fp32): PixCorr[q,p] = sum_c L[c,q]*M[c,p]
__global__ void k_gemm1() {
    int bs = blockIdx.z;
    int b = bs >> 1, s = bs & 1;
    const float* A  = g_ds + (size_t)(b*3 + s)*NC*NQ;
    const float* Bm = g_ds + (size_t)(b*3 + 2)*NC*NQ;
    float* Cout = g_bufA + (size_t)bs*NQ*NQ;
    __shared__ float As[16][64];
    __shared__ float Bs[16][64];
    int tx = threadIdx.x;
    int m0 = blockIdx.x*64, n0 = blockIdx.y*64;
    int lk = tx >> 4, lm = (tx & 15) * 4;
    int lr = tx >> 4, lc = tx & 15;
    float acc[4][4];
    #pragma unroll
    for (int i=0;i<4;i++)
        #pragma unroll
        for (int j=0;j<4;j++) acc[i][j] = 0.f;
    for (int k0 = 0; k0 < NC; k0 += 16) {
        *(float4*)&As[lk][lm] = *(const float4*)&A [(size_t)(k0+lk)*NQ + m0 + lm];
        *(float4*)&Bs[lk][lm] = *(const float4*)&Bm[(size_t)(k0+lk)*NQ + n0 + lm];
        __syncthreads();
        #pragma unroll
        for (int kk = 0; kk < 16; ++kk) {
            float4 av = *(const float4*)&As[kk][lr*4];
            float4 bv = *(const float4*)&Bs[kk][lc*4];
            float a[4] = {av.x, av.y, av.z, av.w};
            float bb[4] = {bv.x, bv.y, bv.z, bv.w};
            #pragma unroll
            for (int i=0;i<4;i++)
                #pragma unroll
                for (int j=0;j<4;j++) acc[i][j] += a[i]*bb[j];
        }
        __syncthreads();
    }
    #pragma unroll
    for (int i=0;i<4;i++) {
        float4 v = make_float4(acc[i][0],acc[i][1],acc[i][2],acc[i][3]);
        *(float4*)&Cout[(size_t)(m0+lr*4+i)*NQ + n0 + lc*4] = v;
    }
}

// ---------- pass A (dj): D1[q][p] = sum_dj [qw+dj, pw+dj in range] C[q+dj][p+dj]
// bufA -> bufB
__global__ void k_passA() {
    long long idx = (long long)blockIdx.x*blockDim.x + threadIdx.x;
    const long long total = (long long)NB*2*NQ*NQ;
    if (idx >= total) return;
    int p = (int)(idx % NQ);
    long long t = idx / NQ;
    int q = (int)(t % NQ);
    int bs = (int)(t / NQ);
    const float* __restrict__ C = g_bufA + (size_t)bs*NQ*NQ;
    int qw = q % HS, pw = p % HS;
    float acc = C[(size_t)q*NQ + p];
    if (qw > 0    && pw > 0   ) acc += C[(size_t)(q-1)*NQ + (p-1)];
    if (qw < HS-1 && pw < HS-1) acc += C[(size_t)(q+1)*NQ + (p+1)];
    g_bufB[idx] = acc;
}

// ---------- pass B (di): psum[q][p] = sum_di [qh+di, ph+di in range] D1[q+di*HS][p+di*HS]
// then multiply by ninv[q].  bufB -> bufA
__global__ void k_passB() {
    long long idx = (long long)blockIdx.x*blockDim.x + threadIdx.x;
    const long long total = (long long)NB*2*NQ*NQ;
    if (idx >= total) return;
    int p = (int)(idx % NQ);
    long long t = idx / NQ;
    int q = (int)(t % NQ);
    int bs = (int)(t / NQ);
    const float* __restrict__ D = g_bufB + (size_t)bs*NQ*NQ;
    int qh = q / HS, ph = p / HS;
    float acc = D[(size_t)q*NQ + p];
    if (qh > 0    && ph > 0   ) acc += D[(size_t)(q-HS)*NQ + (p-HS)];
    if (qh < HS-1 && ph < HS-1) acc += D[(size_t)(q+HS)*NQ + (p+HS)];
    g_bufA[idx] = acc * g_ninv[bs*NQ + q];
}

// ---------- pass C (fuse1, flat diag): bufA -> bufB
__global__ void k_passC() {
    long long idx = (long long)blockIdx.x*blockDim.x + threadIdx.x;
    const long long total = (long long)NB*2*NQ*NQ;
    if (idx >= total) return;
    int p = (int)(idx % NQ);
    long long t = idx / NQ;
    int q = (int)(t % NQ);
    int bs = (int)(t / NQ);
    const float* __restrict__ S = g_bufA + (size_t)bs*NQ*NQ;
    float acc = S[(size_t)q*NQ + p];
    if (q > 0    && p > 0   ) acc += S[(size_t)(q-1)*NQ + (p-1)];
    if (q < NQ-1 && p < NQ-1) acc += S[(size_t)(q+1)*NQ + (p+1)];
    g_bufB[idx] = acc;
}

// ---------- pass D (fuse2, transposed-flat diag): bufB -> bufA
// xm = (xh>0) ? x-HS : (HS-1)*HS + xw-1 ; xp = (xh<HS-1) ? x+HS : xw+1
__global__ void k_passD() {
    long long idx = (long long)blockIdx.x*blockDim.x + threadIdx.x;
    const long long total = (long long)NB*2*NQ*NQ;
    if (idx >= total) return;
    int p = (int)(idx % NQ);
    long long t = idx / NQ;
    int q = (int)(t % NQ);
    int bs = (int)(t / NQ);
    const float* __restrict__ F = g_bufB + (size_t)bs*NQ*NQ;
    int qh = q/HS, qw = q - (q/HS)*HS;
    int ph = p/HS, pw = p - (p/HS)*HS;
    float acc = F[(size_t)q*NQ + p];
    if (q > 0 && p > 0) {
        int qm = (qh > 0) ? (q - HS) : ((HS-1)*HS + qw - 1);
        int pm = (ph > 0) ? (p - HS) : ((HS-1)*HS + pw - 1);
        acc += F[(size_t)qm*NQ + pm];
    }
    if (q < NQ-1 && p < NQ-1) {
        int qp = (qh < HS-1) ? (q + HS) : (qw + 1);
        int pp = (ph < HS-1) ? (p + HS) : (pw + 1);
        acc += F[(size_t)qp*NQ + pp];
    }
    g_bufA[idx] = acc;
}

// --------------- softmax stats: per (bs,p) max over q and 1/sum(exp) (reads bufA)
__global__ void k_softmax_stats() {
    int bs = blockIdx.y;
    int p0 = blockIdx.x * 64;
    const float* __restrict__ F = g_bufA + (size_t)bs*NQ*NQ;
    int px = threadIdx.x & 63;
    int qy = threadIdx.x >> 6;        // 0..3
    int p = p0 + px;
    __shared__ float red[4][64];
    float mx = -3.4e38f;
    for (int q = qy; q < NQ; q += 4) mx = fmaxf(mx, F[(size_t)q*NQ + p]);
    red[qy][px] = mx;
    __syncthreads();
    mx = fmaxf(fmaxf(red[0][px], red[1][px]), fmaxf(red[2][px], red[3][px]));
    __syncthreads();
    float sm = 0.f;
    for (int q = qy; q < NQ; q += 4) sm += __expf(SCL * (F[(size_t)q*NQ + p] - mx));
    red[qy][px] = sm;
    __syncthreads();
    if (qy == 0) {
        g_smax[bs*NQ + p] = mx;
        g_sinv[bs*NQ + p] = 1.0f / (red[0][px] + red[1][px] + red[2][px] + red[3][px]);
    }
}

// --------------- attnT: transposed, normalized attn as half (bufA -> g_ATh)
__global__ void k_attnT() {
    __shared__ float tile[32][33];
    int bs = blockIdx.z;
    int q0 = blockIdx.x * 32, p0 = blockIdx.y * 32;
    const float* __restrict__ F = g_bufA + (size_t)bs*NQ*NQ;
    __half* __restrict__ O = g_ATh + (size_t)bs*NQ*NQ;
    int tx = threadIdx.x, ty = threadIdx.y;  // 32 x 8
    for (int r = ty; r < 32; r += 8)
        tile[r][tx] = F[(size_t)(q0+r)*NQ + p0 + tx];
    __syncthreads();
    for (int r = ty; r < 32; r += 8) {
        int p = p0 + r;
        float e = __expf(SCL * (tile[tx][r] - g_smax[bs*NQ + p])) * g_sinv[bs*NQ + p];
        O[(size_t)p*NQ + q0 + tx] = __float2half_rn(e);
    }
}

// --------------- build paste operand G[bs][m][q] as half, 8 q per thread
__global__ void k_buildG(const float* __restrict__ raw_left,
                         const float* __restrict__ raw_right) {
    int idx = blockIdx.x*blockDim.x + threadIdx.x;
    const int total8 = NB*2*MROWS*(NQ/8);
    if (idx >= total8) return;
    int q8 = (idx % (NQ/8)) * 8;
    int t = idx / (NQ/8);
    int m = t % MROWS;
    int bs = t / MROWS;
    int b = bs >> 1, s = bs & 1;
    int c = m >> 4;
    int o = m & 15;
    int dy = (o >> 2) - 1, dx = (o & 3) - 1;
    int qh = q8 / HS, qw0 = q8 - (q8/HS)*HS;
    int y = 2*qh + dy;
    const float* raw = (s ? raw_right : raw_left) + (size_t)(b*NC + c)*FH*FW;
    __half hv[8];
    if (y >= 0 && y < FH) {
        const float* rrow = raw + (size_t)y*FW;
        #pragma unroll
        for (int j = 0; j < 8; ++j) {
            int x = 2*(qw0 + j) + dx;
            hv[j] = (x >= 0 && x < FW) ? __float2half_rn(rrow[x]) : __half(0.f);
        }
    } else {
        #pragma unroll
        for (int j = 0; j < 8; ++j) hv[j] = __half(0.f);
    }
    *(uint4*)&g_Gh[(size_t)(bs*MROWS + m)*NQ + q8] = *(uint4*)hv;
}

// ------------- GEMM2 (mma.sync fp16, f32 accum): T[m,p] = sum_q G[m,q] * attnT[p,q]
__device__ __forceinline__ void mma_f16(float* c, uint32_t a0, uint32_t a1,
                                        uint32_t a2, uint32_t a3,
                                        uint32_t b0, uint32_t b1) {
    asm volatile(
        "mma.sync.aligned.m16n8k16.row.col.f32.f16.f16.f32 "
        "{%0,%1,%2,%3}, {%4,%5,%6,%7}, {%8,%9}, {%0,%1,%2,%3};"
        : "+f"(c[0]), "+f"(c[1]), "+f"(c[2]), "+f"(c[3])
        : "r"(a0), "r"(a1), "r"(a2), "r"(a3), "r"(b0), "r"(b1));
}

__global__ void __launch_bounds__(256) k_gemm2h() {
    extern __shared__ char smx[];
    const int bs = blockIdx.z;
    const __half* __restrict__ Gm = g_Gh  + (size_t)bs*MROWS*NQ;
    const __half* __restrict__ Bm = g_ATh + (size_t)bs*NQ*NQ;
    float* __restrict__ Tm = g_T + (size_t)bs*MROWS*NQ;
    const int m0 = blockIdx.x * 128, n0 = blockIdx.y * 128;
    const int t = threadIdx.x;
    const int lane = t & 31, wid = t >> 5;
    const int wm = wid & 1, wn = wid >> 1;

    const int prow = t >> 1, ps = t & 1;
    const int pmt = prow >> 4, prr = prow & 15;
    const int pgA = prr & 7;
    const int hwA = (prr >> 3) << 3;
    const int pnt = prow >> 3, pgB = prow & 7;
    const bool pBvalid = (n0 + prow) < NQ;

    uint32_t al[4], ah[4], bl[4], bh[4];

    float acc[4][4][4];
    #pragma unroll
    for (int i=0;i<4;i++)
        #pragma unroll
        for (int j=0;j<4;j++)
            #pragma unroll
            for (int k=0;k<4;k++) acc[i][j][k] = 0.f;

    {
        const uint4* pa = (const uint4*)(Gm + (size_t)(m0+prow)*NQ + ps*16);
        uint4 lo = pa[0], hi = pa[1];
        al[0]=lo.x; al[1]=lo.y; al[2]=lo.z; al[3]=lo.w;
        ah[0]=hi.x; ah[1]=hi.y; ah[2]=hi.z; ah[3]=hi.w;
        if (pBvalid) {
            const uint4* pb = (const uint4*)(Bm + (size_t)(n0+prow)*NQ + ps*16);
            uint4 blo = pb[0], bhi = pb[1];
            bl[0]=blo.x; bl[1]=blo.y; bl[2]=blo.z; bl[3]=blo.w;
            bh[0]=bhi.x; bh[1]=bhi.y; bh[2]=bhi.z; bh[3]=bhi.w;
        } else {
            #pragma unroll
            for (int j=0;j<4;j++) { bl[j]=0u; bh[j]=0u; }
        }
    }

    const int NTILES = NQ / KT;
    for (int it = 0; it < NTILES; ++it) {
        char* base = smx + (it & 1) * 16384;
        char* Asl = base;
        char* Bsl = base + 8192;

        {
            char* aw = Asl + ((ps*8 + pmt)*32 + pgA*4) * 16 + hwA;
            char* bw = Bsl + ((ps*16 + pnt)*32 + pgB*4) * 8;
            #pragma unroll
            for (int j = 0; j < 4; ++j) {
                *(uint2*)(aw + j*16) = make_uint2(al[j], ah[j]);
                *(uint2*)(bw + j*8)  = make_uint2(bl[j], bh[j]);
            }
        }
        __syncthreads();

        if (it + 1 < NTILES) {
            int k0n = (it + 1) * KT;
            const uint4* pa = (const uint4*)(Gm + (size_t)(m0+prow)*NQ + k0n + ps*16);
            uint4 lo = pa[0], hi = pa[1];
            al[0]=lo.x; al[1]=lo.y; al[2]=lo.z; al[3]=lo.w;
            ah[0]=hi.x; ah[1]=hi.y; ah[2]=hi.z; ah[3]=hi.w;
            if (pBvalid) {
                const uint4* pb = (const uint4*)(Bm + (size_t)(n0+prow)*NQ + k0n + ps*16);
                uint4 blo = pb[0], bhi = pb[1];
                bl[0]=blo.x; bl[1]=blo.y; bl[2]=blo.z; bl[3]=blo.w;
                bh[0]=bhi.x; bh[1]=bhi.y; bh[2]=bhi.z; bh[3]=bhi.w;
            }
        }

        #pragma unroll
        for (int s = 0; s < 2; ++s) {
            uint4 af[4]; uint2 bf[4];
            #pragma unroll
            for (int mt = 0; mt < 4; ++mt)
                af[mt] = *(const uint4*)(Asl + (((s*8 + wm*4 + mt)*32 + lane) * 16));
            #pragma unroll
            for (int nt = 0; nt < 4; ++nt)
                bf[nt] = *(const uint2*)(Bsl + (((s*16 + wn*4 + nt)*32 + lane) * 8));
            #pragma unroll
            for (int mt = 0; mt < 4; ++mt)
                #pragma unroll
                for (int nt = 0; nt < 4; ++nt)
                    mma_f16(acc[mt][nt], af[mt].x, af[mt].z, af[mt].y, af[mt].w,
                            bf[nt].x, bf[nt].y);
        }
    }

    #pragma unroll
    for (int mt = 0; mt < 4; ++mt) {
        int m = m0 + wm*64 + mt*16 + (lane >> 2);
        #pragma unroll
        for (int nt = 0; nt < 4; ++nt) {
            int n = n0 + wn*32 + nt*8 + 2*(lane & 3);
            if (n < NQ) {
                *(float2*)&Tm[(size_t)m*NQ + n]     = make_float2(acc[mt][nt][0], acc[mt][nt][1]);
                *(float2*)&Tm[(size_t)(m+8)*NQ + n] = make_float2(acc[mt][nt][2], acc[mt][nt][3]);
            }
        }
    }
}

// ------------- gather epilogue + cosine-window blend -> output (2,128,80,80)
__global__ void k_combine(float* __restrict__ out) {
    int idx = blockIdx.x*blockDim.x + threadIdx.x;
    const int total = NB*NC*FH*FW;
    if (idx >= total) return;
    int X = idx % FW; int t = idx / FW;
    int Y = t % FH; t /= FH;
    int c = t % NC; int b = t / NC;

    int dys[2], hh[2]; int ny = 0;
    if ((Y & 1) == 0) {
        dys[ny] = 0; hh[ny] = Y >> 1; ny++;
        if (Y >= 2) { dys[ny] = 2; hh[ny] = (Y-2) >> 1; ny++; }
    } else {
        dys[ny] = 1; hh[ny] = (Y-1) >> 1; ny++;
        if (Y <= 2*HS - 3) { dys[ny] = -1; hh[ny] = (Y+1) >> 1; ny++; }
    }
    int dxs[2], ww[2]; int nx = 0;
    if ((X & 1) == 0) {
        dxs[nx] = 0; ww[nx] = X >> 1; nx++;
        if (X >= 2) { dxs[nx] = 2; ww[nx] = (X-2) >> 1; nx++; }
    } else {
        dxs[nx] = 1; ww[nx] = (X-1) >> 1; nx++;
        if (X <= 2*HS - 3) { dxs[nx] = -1; ww[nx] = (X+1) >> 1; nx++; }
    }

    const float PI = 3.14159265358979323846f;
    float wl = 0.5f*(1.f + cosf(PI * (float)X        / (float)(FW-1)));
    float wr = 0.5f*(1.f + cosf(PI * (float)(FW-1-X) / (float)(FW-1)));

    float res = 0.f;
    for (int s = 0; s < 2; ++s) {
        const float* T = g_T + (size_t)(b*2 + s)*MROWS*NQ;
        float acc = 0.f;
        for (int iy = 0; iy < ny; ++iy) {
            for (int ix = 0; ix < nx; ++ix) {
                int m = c*16 + (dys[iy]+1)*4 + (dxs[ix]+1);
                acc += T[(size_t)m*NQ + hh[iy]*HS + ww[ix]];
            }
        }
        res += (s == 0 ? wl : wr) * 0.25f * acc;
    }
    out[idx] = res;
}

// ------------------------------------------------------------------ launcher
extern "C" void kernel_launch(void* const* d_in, const int* in_sizes, int n_in,
                              void* d_out, int out_size) {
    const float* left      = (const float*)d_in[0];
    const float* right     = (const float*)d_in[1];
    const float* mid       = (const float*)d_in[2];
    const float* raw_left  = (const float*)d_in[3];
    const float* raw_right = (const float*)d_in[4];
    float* outp = (float*)d_out;

    cudaFuncSetAttribute(k_gemm2h, cudaFuncAttributeMaxDynamicSharedMemorySize, G2_SMEM);

    int t1 = NB*3*NC*NQ;
    k_downsample<<<(t1+255)/256, 256>>>(left, right, mid);
    int t2 = NB*2*NQ;
    k_sumsq<<<(t2+127)/128, 128>>>();
    k_norm<<<(t2+127)/128, 128>>>();

    dim3 g1(NQ/64, NQ/64, NB*2);
    k_gemm1<<<g1, 256>>>();

    long long tp = (long long)NB*2*NQ*NQ;
    int nbElem = (int)((tp + 255) / 256);
    k_passA<<<nbElem, 256>>>();
    k_passB<<<nbElem, 256>>>();
    k_passC<<<nbElem, 256>>>();
    k_passD<<<nbElem, 256>>>();

    k_softmax_stats<<<dim3(NQ/64, NB*2), 256>>>();
    k_attnT<<<dim3(NQ/32, NQ/32, NB*2), dim3(32, 8)>>>();

    int tg8 = NB*2*MROWS*(NQ/8);
    k_buildG<<<(tg8+255)/256, 256>>>(raw_left, raw_right);

    dim3 g2(MROWS/128, (NQ+127)/128, NB*2);
    k_gemm2h<<<g2, 256, G2_SMEM>>>();

    int to = NB*NC*FH*FW;
    k_combine<<<(to+255)/256, 256>>>(outp);
}

// round 10
// speedup vs baseline: 1.1202x; 1.0292x over previous
#include <cuda_runtime.h>
#include <cuda_fp16.h>
#include <math.h>
#include <stdint.h>

// Problem constants
#define NB 2
#define NC 128
#define FH 80
#define FW 80
#define HS 40            // downsampled H=W
#define NQ 1600          // HS*HS
#define NEPS 0.1152f     // 1152 * EPS
#define SCL 10.0f
#define MROWS 2048       // NC * 16 offsets

// fp16 mma GEMM2 config
#define KT 32
#define G2_SMEM 32768

// Static scratch
__device__ float  g_ds[NB*3*NC*NQ];          // downsampled [b][img][c][q] (fp32)
__device__ __align__(16) __half g_dsh[NB*3*NQ*256];  // [b][img][q][hi(128)|lo(128)]
__device__ float  g_E[NB*2*NQ];
__device__ float  g_ninv[NB*2*NQ];
__device__ float  g_smax[NB*2*NQ];
__device__ float  g_sinv[NB*2*NQ];
__device__ float  g_bufA[NB*2*NQ*NQ];        // ping
__device__ float  g_bufB[NB*2*NQ*NQ];        // pong
__device__ __align__(16) __half g_Gh[NB*2*MROWS*NQ];
__device__ __align__(16) __half g_ATh[NB*2*NQ*NQ];
__device__ float  g_T[NB*2*MROWS*NQ];

// ---------------------------------------------------------------- downsample
__global__ void k_downsample(const float* __restrict__ left,
                             const float* __restrict__ right,
                             const float* __restrict__ mid) {
    int idx = blockIdx.x * blockDim.x + threadIdx.x;
    const int total = NB*3*NC*NQ;
    if (idx >= total) return;
    int q = idx % NQ;
    int t = idx / NQ;
    int c = t % NC; t /= NC;
    int img = t % 3; int b = t / 3;
    const float* src = (img == 0) ? left : (img == 1 ? right : mid);
    int qh = q / HS, qw = q % HS;
    g_ds[idx] = src[(size_t)((b*NC + c)*FH + 2*qh)*FW + 2*qw];
}

// ---------------- transpose-convert g_ds [c][q] -> g_dsh [q][hi|lo] (halves)
__global__ void k_cvt() {
    __shared__ float tile[32][33];
    int img = blockIdx.z;                    // b*3+img composite (0..5)
    int q0 = blockIdx.x * 32, c0 = blockIdx.y * 32;
    const float* __restrict__ src = g_ds + (size_t)img*NC*NQ;
    __half* __restrict__ dst = g_dsh + (size_t)img*NQ*256;
    int tx = threadIdx.x, ty = threadIdx.y;  // 32 x 8
    for (int r = ty; r < 32; r += 8)
        tile[r][tx] = src[(size_t)(c0+r)*NQ + q0 + tx];
    __syncthreads();
    for (int r = ty; r < 32; r += 8) {
        int q = q0 + r, c = c0 + tx;
        float v = tile[tx][r];
        __half hi = __float2half_rn(v);
        __half lo = __float2half_rn(v - __half2float(hi));
        dst[(size_t)q*256 + c]       = hi;
        dst[(size_t)q*256 + 128 + c] = lo;
    }
}

// ------------------------------------------------- channel sum-of-squares
__global__ void k_sumsq() {
    int idx = blockIdx.x*blockDim.x + threadIdx.x;
    const int total = NB*2*NQ;
    if (idx >= total) return;
    int q = idx % NQ; int t = idx / NQ;
    int s = t % 2; int b = t / 2;
    const float* p = g_ds + (size_t)(b*3 + s)*NC*NQ + q;
    float acc = 0.f;
    #pragma unroll 8
    for (int c = 0; c < NC; ++c) { float v = p[(size_t)c*NQ]; acc += v*v; }
    g_E[idx] = acc;
}

// -------------------------------------------------- patch norm
__global__ void k_norm() {
    int idx = blockIdx.x*blockDim.x + threadIdx.x;
    const int total = NB*2*NQ;
    if (idx >= total) return;
    int q = idx % NQ; int bs = idx / NQ;
    int qh = q/HS, qw = q%HS;
    float acc = NEPS;
    for (int di=-1; di<=1; ++di) {
        int h = qh+di; if (h < 0 || h >= HS) continue;
        for (int dj=-1; dj<=1; ++dj) {
            int w = qw+dj; if (w < 0 || w >= HS) continue;
            acc += g_E[bs*NQ + h*HS + w];
        }
    }
    g_ninv[idx] = rsqrtf(acc);
}

// ------------- shared fp16 mma helper
__device__ __forceinline__ void mma_f16(float* c, uint32_t a0, uint32_t a1,
                                        uint32_t a2, uint32_t a3,
                                        uint32_t b0, uint32_t b1) {
    asm volatile(
        "mma.sync.aligned.m16n8k16.row.col.f32.f16.f16.f32 "
        "{%0,%1,%2,%3}, {%4,%5,%6,%7}, {%8,%9}, {%0,%1,%2,%3};"
        : "+f"(c[0]), "+f"(c[1]), "+f"(c[2]), "+f"(c[3])
        : "r"(a0), "r"(a1), "r"(a2), "r"(a3), "r"(b0), "r"(b1));
}

// ------------- GEMM1 (split-fp16, 3 products = fp32-quality):
// PixCorr[q,p] = sum_c L[c,q]*M[c,p]; A = Lt [q][hi|lo], B = Mt [p][hi|lo]
// CTA 128x128, K = 128 (4 tiles of 32), 8 warps (2m x 4n).
__global__ void __launch_bounds__(256) k_gemm1h() {
    __shared__ char smx[32768];   // Ahi 8K | Alo 8K | Bhi 8K | Blo 8K
    const int bs = blockIdx.z;
    const int b = bs >> 1, s = bs & 1;
    const __half* __restrict__ Aq = g_dsh + (size_t)(b*3 + s)*NQ*256;
    const __half* __restrict__ Bp = g_dsh + (size_t)(b*3 + 2)*NQ*256;
    float* __restrict__ Cout = g_bufA + (size_t)bs*NQ*NQ;
    const int m0 = blockIdx.x * 128, n0 = blockIdx.y * 128;
    const int t = threadIdx.x;
    const int lane = t & 31, wid = t >> 5;
    const int wm = wid & 1, wn = wid >> 1;

    const int prow = t >> 1, ps = t & 1;
    const int pmt = prow >> 4, prr = prow & 15;
    const int pgA = prr & 7;
    const int hwA = (prr >> 3) << 3;
    const int pnt = prow >> 3, pgB = prow & 7;
    const int rowA = (m0 + prow < NQ) ? (m0 + prow) : (NQ - 1);
    const int rowB = (n0 + prow < NQ) ? (n0 + prow) : (NQ - 1);

    char* Ahi = smx;
    char* Alo = smx + 8192;
    char* Bhi = smx + 16384;
    char* Blo = smx + 24576;

    float acc[4][4][4];
    #pragma unroll
    for (int i=0;i<4;i++)
        #pragma unroll
        for (int j=0;j<4;j++)
            #pragma unroll
            for (int k=0;k<4;k++) acc[i][j][k] = 0.f;

    for (int kt = 0; kt < 4; ++kt) {
        const int k0 = kt * KT;
        // stage 4 sub-operands (hi/lo for A and B), 2 uint4 each
        uint4 ah_lo = *(const uint4*)(Aq + (size_t)rowA*256 + k0 + ps*16);
        uint4 al_lo = *(const uint4*)(Aq + (size_t)rowA*256 + 128 + k0 + ps*16);
        uint4 bh_lo = *(const uint4*)(Bp + (size_t)rowB*256 + k0 + ps*16);
        uint4 bl_lo = *(const uint4*)(Bp + (size_t)rowB*256 + 128 + k0 + ps*16);
        // scatter into fragment-permuted smem (same scheme as gemm2h)
        {
            uint32_t a0[4] = {ah_lo.x, ah_lo.y, ah_lo.z, ah_lo.w};
            uint32_t a1[4] = {al_lo.x, al_lo.y, al_lo.z, al_lo.w};
            uint32_t b0[4] = {bh_lo.x, bh_lo.y, bh_lo.z, bh_lo.w};
            uint32_t b1[4] = {bl_lo.x, bl_lo.y, bl_lo.z, bl_lo.w};
            // NOTE: each staged uint4 covers halves [k0+ps*16, +16); within the
            // slot scheme the first uint4 holds k 0-7, second k 8-15 of the chunk.
            // We must load BOTH 8-half groups per sub-operand:
            // reinterpret: a uint4 = 8 halves = k 0..7? No: uint4 = 16B = 8 halves.
            // The 16-half chunk needs two uint4s.
            (void)a0; (void)a1; (void)b0; (void)b1;
        }
        // --- correct staging: two uint4 per sub-operand (16 halves = one chunk)
        {
            const uint4* pa = (const uint4*)(Aq + (size_t)rowA*256 + k0 + ps*16);
            uint4 lo = pa[0]; uint4 hi = ((const uint4*)(Aq + (size_t)rowA*256 + k0 + ps*16))[0];
            (void)lo; (void)hi;
        }
        // (see below: full staging done inline)
        {
            const __half* abase = Aq + (size_t)rowA*256 + k0 + ps*16;
            const __half* bbase = Bp + (size_t)rowB*256 + k0 + ps*16;
            uint4 Ah0 = *(const uint4*)(abase);          // k 0-7 of chunk (hi part)
            uint4 Ah1 = *(const uint4*)(abase + 8);      // k 8-15
            uint4 Al0 = *(const uint4*)(abase + 128);
            uint4 Al1 = *(const uint4*)(abase + 136);
            uint4 Bh0 = *(const uint4*)(bbase);
            uint4 Bh1 = *(const uint4*)(bbase + 8);
            uint4 Bl0 = *(const uint4*)(bbase + 128);
            uint4 Bl1 = *(const uint4*)(bbase + 136);
            uint32_t l0[4], h0[4];
            char* aw; char* bw;
            // A-hi
            l0[0]=Ah0.x; l0[1]=Ah0.y; l0[2]=Ah0.z; l0[3]=Ah0.w;
            h0[0]=Ah1.x; h0[1]=Ah1.y; h0[2]=Ah1.z; h0[3]=Ah1.w;
            aw = Ahi + ((ps*8 + pmt)*32 + pgA*4) * 16 + hwA;
            #pragma unroll
            for (int j = 0; j < 4; ++j)
                *(uint2*)(aw + j*16) = make_uint2(l0[j], h0[j]);
            // A-lo
            l0[0]=Al0.x; l0[1]=Al0.y; l0[2]=Al0.z; l0[3]=Al0.w;
            h0[0]=Al1.x; h0[1]=Al1.y; h0[2]=Al1.z; h0[3]=Al1.w;
            aw = Alo + ((ps*8 + pmt)*32 + pgA*4) * 16 + hwA;
            #pragma unroll
            for (int j = 0; j < 4; ++j)
                *(uint2*)(aw + j*16) = make_uint2(l0[j], h0[j]);
            // B-hi
            l0[0]=Bh0.x; l0[1]=Bh0.y; l0[2]=Bh0.z; l0[3]=Bh0.w;
            h0[0]=Bh1.x; h0[1]=Bh1.y; h0[2]=Bh1.z; h0[3]=Bh1.w;
            bw = Bhi + ((ps*16 + pnt)*32 + pgB*4) * 8;
            #pragma unroll
            for (int j = 0; j < 4; ++j)
                *(uint2*)(bw + j*8) = make_uint2(l0[j], h0[j]);
            // B-lo
            l0[0]=Bl0.x; l0[1]=Bl0.y; l0[2]=Bl0.z; l0[3]=Bl0.w;
            h0[0]=Bl1.x; h0[1]=Bl1.y; h0[2]=Bl1.z; h0[3]=Bl1.w;
            bw = Blo + ((ps*16 + pnt)*32 + pgB*4) * 8;
            #pragma unroll
            for (int j = 0; j < 4; ++j)
                *(uint2*)(bw + j*8) = make_uint2(l0[j], h0[j]);
        }
        __syncthreads();

        #pragma unroll
        for (int ss = 0; ss < 2; ++ss) {
            uint4 afh[4], afl[4]; uint2 bfh[4], bfl[4];
            #pragma unroll
            for (int mt = 0; mt < 4; ++mt) {
                afh[mt] = *(const uint4*)(Ahi + (((ss*8 + wm*4 + mt)*32 + lane) * 16));
                afl[mt] = *(const uint4*)(Alo + (((ss*8 + wm*4 + mt)*32 + lane) * 16));
            }
            #pragma unroll
            for (int nt = 0; nt < 4; ++nt) {
                bfh[nt] = *(const uint2*)(Bhi + (((ss*16 + wn*4 + nt)*32 + lane) * 8));
                bfl[nt] = *(const uint2*)(Blo + (((ss*16 + wn*4 + nt)*32 + lane) * 8));
            }
            #pragma unroll
            for (int mt = 0; mt < 4; ++mt)
                #pragma unroll
                for (int nt = 0; nt < 4; ++nt) {
                    mma_f16(acc[mt][nt], afh[mt].x, afh[mt].z, afh[mt].y, afh[mt].w,
                            bfh[nt].x, bfh[nt].y);
                    mma_f16(acc[mt][nt], afh[mt].x, afh[mt].z, afh[mt].y, afh[mt].w,
                            bfl[nt].x, bfl[nt].y);
                    mma_f16(acc[mt][nt], afl[mt].x, afl[mt].z, afl[mt].y, afl[mt].w,
                            bfh[nt].x, bfh[nt].y);
                }
        }
        __syncthreads();
    }

    #pragma unroll
    for (int mt = 0; mt < 4; ++mt) {
        int m = m0 + wm*64 + mt*16 + (lane >> 2);
        #pragma unroll
        for (int nt = 0; nt < 4; ++nt) {
            int n = n0 + wn*32 + nt*8 + 2*(lane & 3);
            if (n < NQ) {
                if (m < NQ)
                    *(float2*)&Cout[(size_t)m*NQ + n] =
                        make_float2(acc[mt][nt][0], acc[mt][nt][1]);
                if (m + 8 < NQ)
                    *(float2*)&Cout[(size_t)(m+8)*NQ + n] =
                        make_float2(acc[mt][nt][2], acc[mt][nt][3]);
            }
        }
    }
}

// ---------- pass A (dj): bufA -> bufB
__global__ void k_passA() {
    long long idx = (long long)blockIdx.x*blockDim.x + threadIdx.x;
    const long long total = (long long)NB*2*NQ*NQ;
    if (idx >= total) return;
    int p = (int)(idx % NQ);
    long long t = idx / NQ;
    int q = (int)(t % NQ);
    int bs = (int)(t / NQ);
    const float* __restrict__ C = g_bufA + (size_t)bs*NQ*NQ;
    int qw = q % HS, pw = p % HS;
    float acc = C[(size_t)q*NQ + p];
    if (qw > 0    && pw > 0   ) acc += C[(size_t)(q-1)*NQ + (p-1)];
    if (qw < HS-1 && pw < HS-1) acc += C[(size_t)(q+1)*NQ + (p+1)];
    g_bufB[idx] = acc;
}

// ---------- pass B (di) + ninv: bufB -> bufA
__global__ void k_passB() {
    long long idx = (long long)blockIdx.x*blockDim.x + threadIdx.x;
    const long long total = (long long)NB*2*NQ*NQ;
    if (idx >= total) return;
    int p = (int)(idx % NQ);
    long long t = idx / NQ;
    int q = (int)(t % NQ);
    int bs = (int)(t / NQ);
    const float* __restrict__ D = g_bufB + (size_t)bs*NQ*NQ;
    int qh = q / HS, ph = p / HS;
    float acc = D[(size_t)q*NQ + p];
    if (qh > 0    && ph > 0   ) acc += D[(size_t)(q-HS)*NQ + (p-HS)];
    if (qh < HS-1 && ph < HS-1) acc += D[(size_t)(q+HS)*NQ + (p+HS)];
    g_bufA[idx] = acc * g_ninv[bs*NQ + q];
}

// ---------- pass C (fuse1, flat diag): bufA -> bufB
__global__ void k_passC() {
    long long idx = (long long)blockIdx.x*blockDim.x + threadIdx.x;
    const long long total = (long long)NB*2*NQ*NQ;
    if (idx >= total) return;
    int p = (int)(idx % NQ);
    long long t = idx / NQ;
    int q = (int)(t % NQ);
    int bs = (int)(t / NQ);
    const float* __restrict__ S = g_bufA + (size_t)bs*NQ*NQ;
    float acc = S[(size_t)q*NQ + p];
    if (q > 0    && p > 0   ) acc += S[(size_t)(q-1)*NQ + (p-1)];
    if (q < NQ-1 && p < NQ-1) acc += S[(size_t)(q+1)*NQ + (p+1)];
    g_bufB[idx] = acc;
}

// ---------- pass D (fuse2, transposed-flat diag): bufB -> bufA
__global__ void k_passD() {
    long long idx = (long long)blockIdx.x*blockDim.x + threadIdx.x;
    const long long total = (long long)NB*2*NQ*NQ;
    if (idx >= total) return;
    int p = (int)(idx % NQ);
    long long t = idx / NQ;
    int q = (int)(t % NQ);
    int bs = (int)(t / NQ);
    const float* __restrict__ F = g_bufB + (size_t)bs*NQ*NQ;
    int qh = q/HS, qw = q - (q/HS)*HS;
    int ph = p/HS, pw = p - (p/HS)*HS;
    float acc = F[(size_t)q*NQ + p];
    if (q > 0 && p > 0) {
        int qm = (qh > 0) ? (q - HS) : ((HS-1)*HS + qw - 1);
        int pm = (ph > 0) ? (p - HS) : ((HS-1)*HS + pw - 1);
        acc += F[(size_t)qm*NQ + pm];
    }
    if (q < NQ-1 && p < NQ-1) {
        int qp = (qh < HS-1) ? (q + HS) : (qw + 1);
        int pp = (ph < HS-1) ? (p + HS) : (pw + 1);
        acc += F[(size_t)qp*NQ + pp];
    }
    g_bufA[idx] = acc;
}

// --------------- softmax stats, ONLINE single sweep (reads bufA)
__global__ void k_softmax_stats() {
    int bs = blockIdx.y;
    int p0 = blockIdx.x * 64;
    const float* __restrict__ F = g_bufA + (size_t)bs*NQ*NQ;
    int px = threadIdx.x & 63;
    int qy = threadIdx.x >> 6;        // 0..3
    int p = p0 + px;
    __shared__ float redm[4][64], reds[4][64];
    float mx = -3.4e38f, sm = 0.f;
    for (int q = qy; q < NQ; q += 4) {
        float v = F[(size_t)q*NQ + p];
        if (v <= mx) {
            sm += __expf(SCL * (v - mx));
        } else {
            sm = sm * __expf(SCL * (mx - v)) + 1.f;
            mx = v;
        }
    }
    redm[qy][px] = mx;
    reds[qy][px] = sm;
    __syncthreads();
    if (qy == 0) {
        float m0_ = redm[0][px], m1 = redm[1][px], m2 = redm[2][px], m3 = redm[3][px];
        float M = fmaxf(fmaxf(m0_, m1), fmaxf(m2, m3));
        float S = reds[0][px] * __expf(SCL * (m0_ - M))
                + reds[1][px] * __expf(SCL * (m1 - M))
                + reds[2][px] * __expf(SCL * (m2 - M))
                + reds[3][px] * __expf(SCL * (m3 - M));
        g_smax[bs*NQ + p] = M;
        g_sinv[bs*NQ + p] = 1.0f / S;
    }
}

// --------------- attnT: transposed, normalized attn as half (bufA -> g_ATh)
__global__ void k_attnT() {
    __shared__ float tile[32][33];
    int bs = blockIdx.z;
    int q0 = blockIdx.x * 32, p0 = blockIdx.y * 32;
    const float* __restrict__ F = g_bufA + (size_t)bs*NQ*NQ;
    __half* __restrict__ O = g_ATh + (size_t)bs*NQ*NQ;
    int tx = threadIdx.x, ty = threadIdx.y;  // 32 x 8
    for (int r = ty; r < 32; r += 8)
        tile[r][tx] = F[(size_t)(q0+r)*NQ + p0 + tx];
    __syncthreads();
    for (int r = ty; r < 32; r += 8) {
        int p = p0 + r;
        float e = __expf(SCL * (tile[tx][r] - g_smax[bs*NQ + p])) * g_sinv[bs*NQ + p];
        O[(size_t)p*NQ + q0 + tx] = __float2half_rn(e);
    }
}

// --------------- build paste operand G[bs][m][q] as half, 8 q per thread
__global__ void k_buildG(const float* __restrict__ raw_left,
                         const float* __restrict__ raw_right) {
    int idx = blockIdx.x*blockDim.x + threadIdx.x;
    const int total8 = NB*2*MROWS*(NQ/8);
    if (idx >= total8) return;
    int q8 = (idx % (NQ/8)) * 8;
    int t = idx / (NQ/8);
    int m = t % MROWS;
    int bs = t / MROWS;
    int b = bs >> 1, s = bs & 1;
    int c = m >> 4;
    int o = m & 15;
    int dy = (o >> 2) - 1, dx = (o & 3) - 1;
    int qh = q8 / HS, qw0 = q8 - (q8/HS)*HS;
    int y = 2*qh + dy;
    const float* raw = (s ? raw_right : raw_left) + (size_t)(b*NC + c)*FH*FW;
    __half hv[8];
    if (y >= 0 && y < FH) {
        const float* rrow = raw + (size_t)y*FW;
        #pragma unroll
        for (int j = 0; j < 8; ++j) {
            int x = 2*(qw0 + j) + dx;
            hv[j] = (x >= 0 && x < FW) ? __float2half_rn(rrow[x]) : __half(0.f);
        }
    } else {
        #pragma unroll
        for (int j = 0; j < 8; ++j) hv[j] = __half(0.f);
    }
    *(uint4*)&g_Gh[(size_t)(bs*MROWS + m)*NQ + q8] = *(uint4*)hv;
}

// ------------- GEMM2 (mma.sync fp16, f32 accum): T[m,p] = sum_q G[m,q] * attnT[p,q]
__global__ void __launch_bounds__(256) k_gemm2h() {
    extern __shared__ char smx[];
    const int bs = blockIdx.z;
    const __half* __restrict__ Gm = g_Gh  + (size_t)bs*MROWS*NQ;
    const __half* __restrict__ Bm = g_ATh + (size_t)bs*NQ*NQ;
    float* __restrict__ Tm = g_T + (size_t)bs*MROWS*NQ;
    const int m0 = blockIdx.x * 128, n0 = blockIdx.y * 128;
    const int t = threadIdx.x;
    const int lane = t & 31, wid = t >> 5;
    const int wm = wid & 1, wn = wid >> 1;

    const int prow = t >> 1, ps = t & 1;
    const int pmt = prow >> 4, prr = prow & 15;
    const int pgA = prr & 7;
    const int hwA = (prr >> 3) << 3;
    const int pnt = prow >> 3, pgB = prow & 7;
    const bool pBvalid = (n0 + prow) < NQ;

    uint32_t al[4], ah[4], bl[4], bh[4];

    float acc[4][4][4];
    #pragma unroll
    for (int i=0;i<4;i++)
        #pragma unroll
        for (int j=0;j<4;j++)
            #pragma unroll
            for (int k=0;k<4;k++) acc[i][j][k] = 0.f;

    {
        const uint4* pa = (const uint4*)(Gm + (size_t)(m0+prow)*NQ + ps*16);
        uint4 lo = pa[0], hi = pa[1];
        al[0]=lo.x; al[1]=lo.y; al[2]=lo.z; al[3]=lo.w;
        ah[0]=hi.x; ah[1]=hi.y; ah[2]=hi.z; ah[3]=hi.w;
        if (pBvalid) {
            const uint4* pb = (const uint4*)(Bm + (size_t)(n0+prow)*NQ + ps*16);
            uint4 blo = pb[0], bhi = pb[1];
            bl[0]=blo.x; bl[1]=blo.y; bl[2]=blo.z; bl[3]=blo.w;
            bh[0]=bhi.x; bh[1]=bhi.y; bh[2]=bhi.z; bh[3]=bhi.w;
        } else {
            #pragma unroll
            for (int j=0;j<4;j++) { bl[j]=0u; bh[j]=0u; }
        }
    }

    const int NTILES = NQ / KT;
    for (int it = 0; it < NTILES; ++it) {
        char* base = smx + (it & 1) * 16384;
        char* Asl = base;
        char* Bsl = base + 8192;

        {
            char* aw = Asl + ((ps*8 + pmt)*32 + pgA*4) * 16 + hwA;
            char* bw = Bsl + ((ps*16 + pnt)*32 + pgB*4) * 8;
            #pragma unroll
            for (int j = 0; j < 4; ++j) {
                *(uint2*)(aw + j*16) = make_uint2(al[j], ah[j]);
                *(uint2*)(bw + j*8)  = make_uint2(bl[j], bh[j]);
            }
        }
        __syncthreads();

        if (it + 1 < NTILES) {
            int k0n = (it + 1) * KT;
            const uint4* pa = (const uint4*)(Gm + (size_t)(m0+prow)*NQ + k0n + ps*16);
            uint4 lo = pa[0], hi = pa[1];
            al[0]=lo.x; al[1]=lo.y; al[2]=lo.z; al[3]=lo.w;
            ah[0]=hi.x; ah[1]=hi.y; ah[2]=hi.z; ah[3]=hi.w;
            if (pBvalid) {
                const uint4* pb = (const uint4*)(Bm + (size_t)(n0+prow)*NQ + k0n + ps*16);
                uint4 blo = pb[0], bhi = pb[1];
                bl[0]=blo.x; bl[1]=blo.y; bl[2]=blo.z; bl[3]=blo.w;
                bh[0]=bhi.x; bh[1]=bhi.y; bh[2]=bhi.z; bh[3]=bhi.w;
            }
        }

        #pragma unroll
        for (int s = 0; s < 2; ++s) {
            uint4 af[4]; uint2 bf[4];
            #pragma unroll
            for (int mt = 0; mt < 4; ++mt)
                af[mt] = *(const uint4*)(Asl + (((s*8 + wm*4 + mt)*32 + lane) * 16));
            #pragma unroll
            for (int nt = 0; nt < 4; ++nt)
                bf[nt] = *(const uint2*)(Bsl + (((s*16 + wn*4 + nt)*32 + lane) * 8));
            #pragma unroll
            for (int mt = 0; mt < 4; ++mt)
                #pragma unroll
                for (int nt = 0; nt < 4; ++nt)
                    mma_f16(acc[mt][nt], af[mt].x, af[mt].z, af[mt].y, af[mt].w,
                            bf[nt].x, bf[nt].y);
        }
    }

    #pragma unroll
    for (int mt = 0; mt < 4; ++mt) {
        int m = m0 + wm*64 + mt*16 + (lane >> 2);
        #pragma unroll
        for (int nt = 0; nt < 4; ++nt) {
            int n = n0 + wn*32 + nt*8 + 2*(lane & 3);
            if (n < NQ) {
                *(float2*)&Tm[(size_t)m*NQ + n]     = make_float2(acc[mt][nt][0], acc[mt][nt][1]);
                *(float2*)&Tm[(size_t)(m+8)*NQ + n] = make_float2(acc[mt][nt][2], acc[mt][nt][3]);
            }
        }
    }
}

// ------------- gather epilogue + cosine-window blend -> output (2,128,80,80)
__global__ void k_combine(float* __restrict__ out) {
    int idx = blockIdx.x*blockDim.x + threadIdx.x;
    const int total = NB*NC*FH*FW;
    if (idx >= total) return;
    int X = idx % FW; int t = idx / FW;
    int Y = t % FH; t /= FH;
    int c = t % NC; int b = t / NC;

    int dys[2], hh[2]; int ny = 0;
    if ((Y & 1) == 0) {
        dys[ny] = 0; hh[ny] = Y >> 1; ny++;
        if (Y >= 2) { dys[ny] = 2; hh[ny] = (Y-2) >> 1; ny++; }
    } else {
        dys[ny] = 1; hh[ny] = (Y-1) >> 1; ny++;
        if (Y <= 2*HS - 3) { dys[ny] = -1; hh[ny] = (Y+1) >> 1; ny++; }
    }
    int dxs[2], ww[2]; int nx = 0;
    if ((X & 1) == 0) {
        dxs[nx] = 0; ww[nx] = X >> 1; nx++;
        if (X >= 2) { dxs[nx] = 2; ww[nx] = (X-2) >> 1; nx++; }
    } else {
        dxs[nx] = 1; ww[nx] = (X-1) >> 1; nx++;
        if (X <= 2*HS - 3) { dxs[nx] = -1; ww[nx] = (X+1) >> 1; nx++; }
    }

    const float PI = 3.14159265358979323846f;
    float wl = 0.5f*(1.f + cosf(PI * (float)X        / (float)(FW-1)));
    float wr = 0.5f*(1.f + cosf(PI * (float)(FW-1-X) / (float)(FW-1)));

    float res = 0.f;
    for (int s = 0; s < 2; ++s) {
        const float* T = g_T + (size_t)(b*2 + s)*MROWS*NQ;
        float acc = 0.f;
        for (int iy = 0; iy < ny; ++iy) {
            for (int ix = 0; ix < nx; ++ix) {
                int m = c*16 + (dys[iy]+1)*4 + (dxs[ix]+1);
                acc += T[(size_t)m*NQ + hh[iy]*HS + ww[ix]];
            }
        }
        res += (s == 0 ? wl : wr) * 0.25f * acc;
    }
    out[idx] = res;
}

// ------------------------------------------------------------------ launcher
extern "C" void kernel_launch(void* const* d_in, const int* in_sizes, int n_in,
                              void* d_out, int out_size) {
    const float* left      = (const float*)d_in[0];
    const float* right     = (const float*)d_in[1];
    const float* mid       = (const float*)d_in[2];
    const float* raw_left  = (const float*)d_in[3];
    const float* raw_right = (const float*)d_in[4];
    float* outp = (float*)d_out;

    cudaFuncSetAttribute(k_gemm2h, cudaFuncAttributeMaxDynamicSharedMemorySize, G2_SMEM);

    int t1 = NB*3*NC*NQ;
    k_downsample<<<(t1+255)/256, 256>>>(left, right, mid);
    k_cvt<<<dim3(NQ/32, NC/32, NB*3), dim3(32, 8)>>>();
    int t2 = NB*2*NQ;
    k_sumsq<<<(t2+127)/128, 128>>>();
    k_norm<<<(t2+127)/128, 128>>>();

    dim3 g1((NQ+127)/128, (NQ+127)/128, NB*2);   // 13 x 13 x 4
    k_gemm1h<<<g1, 256>>>();

    long long tp = (long long)NB*2*NQ*NQ;
    int nbElem = (int)((tp + 255) / 256);
    k_passA<<<nbElem, 256>>>();
    k_passB<<<nbElem, 256>>>();
    k_passC<<<nbElem, 256>>>();
    k_passD<<<nbElem, 256>>>();

    k_softmax_stats<<<dim3(NQ/64, NB*2), 256>>>();
    k_attnT<<<dim3(NQ/32, NQ/32, NB*2), dim3(32, 8)>>>();

    int tg8 = NB*2*MROWS*(NQ/8);
    k_buildG<<<(tg8+255)/256, 256>>>(raw_left, raw_right);

    dim3 g2(MROWS/128, (NQ+127)/128, NB*2);
    k_gemm2h<<<g2, 256, G2_SMEM>>>();

    int to = NB*NC*FH*FW;
    k_combine<<<(to+255)/256, 256>>>(outp);
}

// round 11
// speedup vs baseline: 1.1868x; 1.0595x over previous
#include <cuda_runtime.h>
#include <cuda_fp16.h>
#include <math.h>
#include <stdint.h>

// Problem constants
#define NB 2
#define NC 128
#define FH 80
#define FW 80
#define HS 40            // downsampled H=W
#define NQ 1600          // HS*HS
#define NEPS 0.1152f     // 1152 * EPS
#define SCL 10.0f
#define MROWS 2048       // NC * 16 offsets

// fp16 mma GEMM2 config
#define KT 32
#define G2_SMEM 32768

// Static scratch
__device__ float  g_ds[NB*3*NC*NQ];          // downsampled [b][img][c][q] (fp32)
__device__ __align__(16) __half g_dsh[NB*3*NQ*256];  // [b][img][q][hi(128)|lo(128)]
__device__ float  g_E[NB*2*NQ];
__device__ float  g_ninv[NB*2*NQ];
__device__ float  g_smax[NB*2*NQ];
__device__ float  g_sinv[NB*2*NQ];
__device__ float  g_bufA[NB*2*NQ*NQ];        // ping
__device__ float  g_bufB[NB*2*NQ*NQ];        // pong
__device__ __align__(16) __half g_Gh[NB*2*MROWS*NQ];
__device__ __align__(16) __half g_ATh[NB*2*NQ*NQ];
__device__ float  g_T[NB*2*MROWS*NQ];

// ---------------------------------------------------------------- downsample
__global__ void k_downsample(const float* __restrict__ left,
                             const float* __restrict__ right,
                             const float* __restrict__ mid) {
    int idx = blockIdx.x * blockDim.x + threadIdx.x;
    const int total = NB*3*NC*NQ;
    if (idx >= total) return;
    int q = idx % NQ;
    int t = idx / NQ;
    int c = t % NC; t /= NC;
    int img = t % 3; int b = t / 3;
    const float* src = (img == 0) ? left : (img == 1 ? right : mid);
    int qh = q / HS, qw = q % HS;
    g_ds[idx] = src[(size_t)((b*NC + c)*FH + 2*qh)*FW + 2*qw];
}

// ---------------- transpose-convert g_ds [c][q] -> g_dsh [q][hi|lo] (halves)
__global__ void k_cvt() {
    __shared__ float tile[32][33];
    int img = blockIdx.z;                    // b*3+img composite (0..5)
    int q0 = blockIdx.x * 32, c0 = blockIdx.y * 32;
    const float* __restrict__ src = g_ds + (size_t)img*NC*NQ;
    __half* __restrict__ dst = g_dsh + (size_t)img*NQ*256;
    int tx = threadIdx.x, ty = threadIdx.y;  // 32 x 8
    for (int r = ty; r < 32; r += 8)
        tile[r][tx] = src[(size_t)(c0+r)*NQ + q0 + tx];
    __syncthreads();
    for (int r = ty; r < 32; r += 8) {
        int q = q0 + r, c = c0 + tx;
        float v = tile[tx][r];
        __half hi = __float2half_rn(v);
        __half lo = __float2half_rn(v - __half2float(hi));
        dst[(size_t)q*256 + c]       = hi;
        dst[(size_t)q*256 + 128 + c] = lo;
    }
}

// ------------------------------------------------- channel sum-of-squares
__global__ void k_sumsq() {
    int idx = blockIdx.x*blockDim.x + threadIdx.x;
    const int total = NB*2*NQ;
    if (idx >= total) return;
    int q = idx % NQ; int t = idx / NQ;
    int s = t % 2; int b = t / 2;
    const float* p = g_ds + (size_t)(b*3 + s)*NC*NQ + q;
    float acc = 0.f;
    #pragma unroll 8
    for (int c = 0; c < NC; ++c) { float v = p[(size_t)c*NQ]; acc += v*v; }
    g_E[idx] = acc;
}

// -------------------------------------------------- patch norm
__global__ void k_norm() {
    int idx = blockIdx.x*blockDim.x + threadIdx.x;
    const int total = NB*2*NQ;
    if (idx >= total) return;
    int q = idx % NQ; int bs = idx / NQ;
    int qh = q/HS, qw = q%HS;
    float acc = NEPS;
    for (int di=-1; di<=1; ++di) {
        int h = qh+di; if (h < 0 || h >= HS) continue;
        for (int dj=-1; dj<=1; ++dj) {
            int w = qw+dj; if (w < 0 || w >= HS) continue;
            acc += g_E[bs*NQ + h*HS + w];
        }
    }
    g_ninv[idx] = rsqrtf(acc);
}

// ------------- shared fp16 mma helper
__device__ __forceinline__ void mma_f16(float* c, uint32_t a0, uint32_t a1,
                                        uint32_t a2, uint32_t a3,
                                        uint32_t b0, uint32_t b1) {
    asm volatile(
        "mma.sync.aligned.m16n8k16.row.col.f32.f16.f16.f32 "
        "{%0,%1,%2,%3}, {%4,%5,%6,%7}, {%8,%9}, {%0,%1,%2,%3};"
        : "+f"(c[0]), "+f"(c[1]), "+f"(c[2]), "+f"(c[3])
        : "r"(a0), "r"(a1), "r"(a2), "r"(a3), "r"(b0), "r"(b1));
}

// ------------- GEMM1 (split-fp16, 3 products = fp32-quality)
__global__ void __launch_bounds__(256) k_gemm1h() {
    __shared__ char smx[32768];   // Ahi 8K | Alo 8K | Bhi 8K | Blo 8K
    const int bs = blockIdx.z;
    const int b = bs >> 1, s = bs & 1;
    const __half* __restrict__ Aq = g_dsh + (size_t)(b*3 + s)*NQ*256;
    const __half* __restrict__ Bp = g_dsh + (size_t)(b*3 + 2)*NQ*256;
    float* __restrict__ Cout = g_bufA + (size_t)bs*NQ*NQ;
    const int m0 = blockIdx.x * 128, n0 = blockIdx.y * 128;
    const int t = threadIdx.x;
    const int lane = t & 31, wid = t >> 5;
    const int wm = wid & 1, wn = wid >> 1;

    const int prow = t >> 1, ps = t & 1;
    const int pmt = prow >> 4, prr = prow & 15;
    const int pgA = prr & 7;
    const int hwA = (prr >> 3) << 3;
    const int pnt = prow >> 3, pgB = prow & 7;
    const int rowA = (m0 + prow < NQ) ? (m0 + prow) : (NQ - 1);
    const int rowB = (n0 + prow < NQ) ? (n0 + prow) : (NQ - 1);

    char* Ahi = smx;
    char* Alo = smx + 8192;
    char* Bhi = smx + 16384;
    char* Blo = smx + 24576;

    float acc[4][4][4];
    #pragma unroll
    for (int i=0;i<4;i++)
        #pragma unroll
        for (int j=0;j<4;j++)
            #pragma unroll
            for (int k=0;k<4;k++) acc[i][j][k] = 0.f;

    for (int kt = 0; kt < 4; ++kt) {
        const int k0 = kt * KT;
        {
            const __half* abase = Aq + (size_t)rowA*256 + k0 + ps*16;
            const __half* bbase = Bp + (size_t)rowB*256 + k0 + ps*16;
            uint4 Ah0 = *(const uint4*)(abase);
            uint4 Ah1 = *(const uint4*)(abase + 8);
            uint4 Al0 = *(const uint4*)(abase + 128);
            uint4 Al1 = *(const uint4*)(abase + 136);
            uint4 Bh0 = *(const uint4*)(bbase);
            uint4 Bh1 = *(const uint4*)(bbase + 8);
            uint4 Bl0 = *(const uint4*)(bbase + 128);
            uint4 Bl1 = *(const uint4*)(bbase + 136);
            uint32_t l0[4], h0[4];
            char* aw; char* bw;
            l0[0]=Ah0.x; l0[1]=Ah0.y; l0[2]=Ah0.z; l0[3]=Ah0.w;
            h0[0]=Ah1.x; h0[1]=Ah1.y; h0[2]=Ah1.z; h0[3]=Ah1.w;
            aw = Ahi + ((ps*8 + pmt)*32 + pgA*4) * 16 + hwA;
            #pragma unroll
            for (int j = 0; j < 4; ++j)
                *(uint2*)(aw + j*16) = make_uint2(l0[j], h0[j]);
            l0[0]=Al0.x; l0[1]=Al0.y; l0[2]=Al0.z; l0[3]=Al0.w;
            h0[0]=Al1.x; h0[1]=Al1.y; h0[2]=Al1.z; h0[3]=Al1.w;
            aw = Alo + ((ps*8 + pmt)*32 + pgA*4) * 16 + hwA;
            #pragma unroll
            for (int j = 0; j < 4; ++j)
                *(uint2*)(aw + j*16) = make_uint2(l0[j], h0[j]);
            l0[0]=Bh0.x; l0[1]=Bh0.y; l0[2]=Bh0.z; l0[3]=Bh0.w;
            h0[0]=Bh1.x; h0[1]=Bh1.y; h0[2]=Bh1.z; h0[3]=Bh1.w;
            bw = Bhi + ((ps*16 + pnt)*32 + pgB*4) * 8;
            #pragma unroll
            for (int j = 0; j < 4; ++j)
                *(uint2*)(bw + j*8) = make_uint2(l0[j], h0[j]);
            l0[0]=Bl0.x; l0[1]=Bl0.y; l0[2]=Bl0.z; l0[3]=Bl0.w;
            h0[0]=Bl1.x; h0[1]=Bl1.y; h0[2]=Bl1.z; h0[3]=Bl1.w;
            bw = Blo + ((ps*16 + pnt)*32 + pgB*4) * 8;
            #pragma unroll
            for (int j = 0; j < 4; ++j)
                *(uint2*)(bw + j*8) = make_uint2(l0[j], h0[j]);
        }
        __syncthreads();

        #pragma unroll
        for (int ss = 0; ss < 2; ++ss) {
            uint4 afh[4], afl[4]; uint2 bfh[4], bfl[4];
            #pragma unroll
            for (int mt = 0; mt < 4; ++mt) {
                afh[mt] = *(const uint4*)(Ahi + (((ss*8 + wm*4 + mt)*32 + lane) * 16));
                afl[mt] = *(const uint4*)(Alo + (((ss*8 + wm*4 + mt)*32 + lane) * 16));
            }
            #pragma unroll
            for (int nt = 0; nt < 4; ++nt) {
                bfh[nt] = *(const uint2*)(Bhi + (((ss*16 + wn*4 + nt)*32 + lane) * 8));
                bfl[nt] = *(const uint2*)(Blo + (((ss*16 + wn*4 + nt)*32 + lane) * 8));
            }
            #pragma unroll
            for (int mt = 0; mt < 4; ++mt)
                #pragma unroll
                for (int nt = 0; nt < 4; ++nt) {
                    mma_f16(acc[mt][nt], afh[mt].x, afh[mt].z, afh[mt].y, afh[mt].w,
                            bfh[nt].x, bfh[nt].y);
                    mma_f16(acc[mt][nt], afh[mt].x, afh[mt].z, afh[mt].y, afh[mt].w,
                            bfl[nt].x, bfl[nt].y);
                    mma_f16(acc[mt][nt], afl[mt].x, afl[mt].z, afl[mt].y, afl[mt].w,
                            bfh[nt].x, bfh[nt].y);
                }
        }
        __syncthreads();
    }

    #pragma unroll
    for (int mt = 0; mt < 4; ++mt) {
        int m = m0 + wm*64 + mt*16 + (lane >> 2);
        #pragma unroll
        for (int nt = 0; nt < 4; ++nt) {
            int n = n0 + wn*32 + nt*8 + 2*(lane & 3);
            if (n < NQ) {
                if (m < NQ)
                    *(float2*)&Cout[(size_t)m*NQ + n] =
                        make_float2(acc[mt][nt][0], acc[mt][nt][1]);
                if (m + 8 < NQ)
                    *(float2*)&Cout[(size_t)(m+8)*NQ + n] =
                        make_float2(acc[mt][nt][2], acc[mt][nt][3]);
            }
        }
    }
}

// ---------- FUSED passes A+B (slab-tiled): bufA -> bufB
// Block owns output slab (bs, qh, ph); loads 3 diagonal input slabs (qh+e, ph+e)
// into smem, applies the (ew) 3-tap diagonal within each slab, sums valid (eh)
// terms, scales by ninv[q]. Exactly reproduces passA followed by passB.
__global__ void __launch_bounds__(256) k_psAB() {
    __shared__ float sl[3][40][40];
    int blk = blockIdx.x;                 // bs*1600 + qh*40 + ph
    int ph = blk % HS; int t2 = blk / HS;
    int qh = t2 % HS; int bs = t2 / HS;
    const float* __restrict__ In = g_bufA + (size_t)bs*NQ*NQ;
    float* __restrict__ Out = g_bufB + (size_t)bs*NQ*NQ;
    const int tid = threadIdx.x;

    #pragma unroll
    for (int e = -1; e <= 1; ++e) {
        int Qh = qh + e, Ph = ph + e;
        if (Qh < 0 || Qh >= HS || Ph < 0 || Ph >= HS) continue;
        const float* base = In + (size_t)(Qh*HS)*NQ + Ph*HS;
        for (int i = tid; i < 400; i += 256) {
            int row = i / 10, c4 = (i % 10) * 4;
            *(float4*)&sl[e+1][row][c4] = *(const float4*)(base + (size_t)row*NQ + c4);
        }
    }
    __syncthreads();

    const float* __restrict__ ninv = g_ninv + bs*NQ;
    const bool em = (qh > 0)    && (ph > 0);
    const bool ez = true;
    const bool ep = (qh < HS-1) && (ph < HS-1);
    for (int i = tid; i < 1600; i += 256) {
        int qw = i / 40, pw = i % 40;
        bool dm = (qw > 0), dp = (qw < HS-1) && (pw < HS-1);
        // note: minus tap needs qw>0 && pw>0; plus tap qw<39 && pw<39
        bool dmm = dm && (pw > 0);
        float acc = 0.f;
        #pragma unroll
        for (int eh = 0; eh < 3; ++eh) {
            bool ok = (eh == 0) ? em : ((eh == 1) ? ez : ep);
            if (!ok) continue;
            float s = sl[eh][qw][pw];
            if (dmm) s += sl[eh][qw-1][pw-1];
            if (dp)  s += sl[eh][qw+1][pw+1];
            acc += s;
        }
        Out[(size_t)(qh*HS + qw)*NQ + ph*HS + pw] = acc * ninv[qh*HS + qw];
    }
}

// ---------- pass C (fuse1, flat diag): bufB -> bufA
__global__ void k_passC() {
    long long idx = (long long)blockIdx.x*blockDim.x + threadIdx.x;
    const long long total = (long long)NB*2*NQ*NQ;
    if (idx >= total) return;
    int p = (int)(idx % NQ);
    long long t = idx / NQ;
    int q = (int)(t % NQ);
    int bs = (int)(t / NQ);
    const float* __restrict__ S = g_bufB + (size_t)bs*NQ*NQ;
    float acc = S[(size_t)q*NQ + p];
    if (q > 0    && p > 0   ) acc += S[(size_t)(q-1)*NQ + (p-1)];
    if (q < NQ-1 && p < NQ-1) acc += S[(size_t)(q+1)*NQ + (p+1)];
    g_bufA[idx] = acc;
}

// ---------- pass D (fuse2, transposed-flat diag): bufA -> bufB
__global__ void k_passD() {
    long long idx = (long long)blockIdx.x*blockDim.x + threadIdx.x;
    const long long total = (long long)NB*2*NQ*NQ;
    if (idx >= total) return;
    int p = (int)(idx % NQ);
    long long t = idx / NQ;
    int q = (int)(t % NQ);
    int bs = (int)(t / NQ);
    const float* __restrict__ F = g_bufA + (size_t)bs*NQ*NQ;
    int qh = q/HS, qw = q - (q/HS)*HS;
    int ph = p/HS, pw = p - (p/HS)*HS;
    float acc = F[(size_t)q*NQ + p];
    if (q > 0 && p > 0) {
        int qm = (qh > 0) ? (q - HS) : ((HS-1)*HS + qw - 1);
        int pm = (ph > 0) ? (p - HS) : ((HS-1)*HS + pw - 1);
        acc += F[(size_t)qm*NQ + pm];
    }
    if (q < NQ-1 && p < NQ-1) {
        int qp = (qh < HS-1) ? (q + HS) : (qw + 1);
        int pp = (ph < HS-1) ? (p + HS) : (pw + 1);
        acc += F[(size_t)qp*NQ + pp];
    }
    g_bufB[idx] = acc;
}

// --------------- softmax stats, ONLINE single sweep (reads bufB)
__global__ void k_softmax_stats() {
    int bs = blockIdx.y;
    int p0 = blockIdx.x * 64;
    const float* __restrict__ F = g_bufB + (size_t)bs*NQ*NQ;
    int px = threadIdx.x & 63;
    int qy = threadIdx.x >> 6;        // 0..3
    int p = p0 + px;
    __shared__ float redm[4][64], reds[4][64];
    float mx = -3.4e38f, sm = 0.f;
    for (int q = qy; q < NQ; q += 4) {
        float v = F[(size_t)q*NQ + p];
        if (v <= mx) {
            sm += __expf(SCL * (v - mx));
        } else {
            sm = sm * __expf(SCL * (mx - v)) + 1.f;
            mx = v;
        }
    }
    redm[qy][px] = mx;
    reds[qy][px] = sm;
    __syncthreads();
    if (qy == 0) {
        float m0_ = redm[0][px], m1 = redm[1][px], m2 = redm[2][px], m3 = redm[3][px];
        float M = fmaxf(fmaxf(m0_, m1), fmaxf(m2, m3));
        float S = reds[0][px] * __expf(SCL * (m0_ - M))
                + reds[1][px] * __expf(SCL * (m1 - M))
                + reds[2][px] * __expf(SCL * (m2 - M))
                + reds[3][px] * __expf(SCL * (m3 - M));
        g_smax[bs*NQ + p] = M;
        g_sinv[bs*NQ + p] = 1.0f / S;
    }
}

// --------------- attnT: transposed, normalized attn as half (bufB -> g_ATh)
__global__ void k_attnT() {
    __shared__ float tile[32][33];
    int bs = blockIdx.z;
    int q0 = blockIdx.x * 32, p0 = blockIdx.y * 32;
    const float* __restrict__ F = g_bufB + (size_t)bs*NQ*NQ;
    __half* __restrict__ O = g_ATh + (size_t)bs*NQ*NQ;
    int tx = threadIdx.x, ty = threadIdx.y;  // 32 x 8
    for (int r = ty; r < 32; r += 8)
        tile[r][tx] = F[(size_t)(q0+r)*NQ + p0 + tx];
    __syncthreads();
    for (int r = ty; r < 32; r += 8) {
        int p = p0 + r;
        float e = __expf(SCL * (tile[tx][r] - g_smax[bs*NQ + p])) * g_sinv[bs*NQ + p];
        O[(size_t)p*NQ + q0 + tx] = __float2half_rn(e);
    }
}

// --------------- build paste operand G[bs][m][q] as half, 8 q per thread
__global__ void k_buildG(const float* __restrict__ raw_left,
                         const float* __restrict__ raw_right) {
    int idx = blockIdx.x*blockDim.x + threadIdx.x;
    const int total8 = NB*2*MROWS*(NQ/8);
    if (idx >= total8) return;
    int q8 = (idx % (NQ/8)) * 8;
    int t = idx / (NQ/8);
    int m = t % MROWS;
    int bs = t / MROWS;
    int b = bs >> 1, s = bs & 1;
    int c = m >> 4;
    int o = m & 15;
    int dy = (o >> 2) - 1, dx = (o & 3) - 1;
    int qh = q8 / HS, qw0 = q8 - (q8/HS)*HS;
    int y = 2*qh + dy;
    const float* raw = (s ? raw_right : raw_left) + (size_t)(b*NC + c)*FH*FW;
    __half hv[8];
    if (y >= 0 && y < FH) {
        const float* rrow = raw + (size_t)y*FW;
        #pragma unroll
        for (int j = 0; j < 8; ++j) {
            int x = 2*(qw0 + j) + dx;
            hv[j] = (x >= 0 && x < FW) ? __float2half_rn(rrow[x]) : __half(0.f);
        }
    } else {
        #pragma unroll
        for (int j = 0; j < 8; ++j) hv[j] = __half(0.f);
    }
    *(uint4*)&g_Gh[(size_t)(bs*MROWS + m)*NQ + q8] = *(uint4*)hv;
}

// ------------- GEMM2 (mma.sync fp16, f32 accum): T[m,p] = sum_q G[m,q] * attnT[p,q]
__global__ void __launch_bounds__(256) k_gemm2h() {
    extern __shared__ char smx[];
    const int bs = blockIdx.z;
    const __half* __restrict__ Gm = g_Gh  + (size_t)bs*MROWS*NQ;
    const __half* __restrict__ Bm = g_ATh + (size_t)bs*NQ*NQ;
    float* __restrict__ Tm = g_T + (size_t)bs*MROWS*NQ;
    const int m0 = blockIdx.x * 128, n0 = blockIdx.y * 128;
    const int t = threadIdx.x;
    const int lane = t & 31, wid = t >> 5;
    const int wm = wid & 1, wn = wid >> 1;

    const int prow = t >> 1, ps = t & 1;
    const int pmt = prow >> 4, prr = prow & 15;
    const int pgA = prr & 7;
    const int hwA = (prr >> 3) << 3;
    const int pnt = prow >> 3, pgB = prow & 7;
    const bool pBvalid = (n0 + prow) < NQ;

    uint32_t al[4], ah[4], bl[4], bh[4];

    float acc[4][4][4];
    #pragma unroll
    for (int i=0;i<4;i++)
        #pragma unroll
        for (int j=0;j<4;j++)
            #pragma unroll
            for (int k=0;k<4;k++) acc[i][j][k] = 0.f;

    {
        const uint4* pa = (const uint4*)(Gm + (size_t)(m0+prow)*NQ + ps*16);
        uint4 lo = pa[0], hi = pa[1];
        al[0]=lo.x; al[1]=lo.y; al[2]=lo.z; al[3]=lo.w;
        ah[0]=hi.x; ah[1]=hi.y; ah[2]=hi.z; ah[3]=hi.w;
        if (pBvalid) {
            const uint4* pb = (const uint4*)(Bm + (size_t)(n0+prow)*NQ + ps*16);
            uint4 blo = pb[0], bhi = pb[1];
            bl[0]=blo.x; bl[1]=blo.y; bl[2]=blo.z; bl[3]=blo.w;
            bh[0]=bhi.x; bh[1]=bhi.y; bh[2]=bhi.z; bh[3]=bhi.w;
        } else {
            #pragma unroll
            for (int j=0;j<4;j++) { bl[j]=0u; bh[j]=0u; }
        }
    }

    const int NTILES = NQ / KT;
    for (int it = 0; it < NTILES; ++it) {
        char* base = smx + (it & 1) * 16384;
        char* Asl = base;
        char* Bsl = base + 8192;

        {
            char* aw = Asl + ((ps*8 + pmt)*32 + pgA*4) * 16 + hwA;
            char* bw = Bsl + ((ps*16 + pnt)*32 + pgB*4) * 8;
            #pragma unroll
            for (int j = 0; j < 4; ++j) {
                *(uint2*)(aw + j*16) = make_uint2(al[j], ah[j]);
                *(uint2*)(bw + j*8)  = make_uint2(bl[j], bh[j]);
            }
        }
        __syncthreads();

        if (it + 1 < NTILES) {
            int k0n = (it + 1) * KT;
            const uint4* pa = (const uint4*)(Gm + (size_t)(m0+prow)*NQ + k0n + ps*16);
            uint4 lo = pa[0], hi = pa[1];
            al[0]=lo.x; al[1]=lo.y; al[2]=lo.z; al[3]=lo.w;
            ah[0]=hi.x; ah[1]=hi.y; ah[2]=hi.z; ah[3]=hi.w;
            if (pBvalid) {
                const uint4* pb = (const uint4*)(Bm + (size_t)(n0+prow)*NQ + k0n + ps*16);
                uint4 blo = pb[0], bhi = pb[1];
                bl[0]=blo.x; bl[1]=blo.y; bl[2]=blo.z; bl[3]=blo.w;
                bh[0]=bhi.x; bh[1]=bhi.y; bh[2]=bhi.z; bh[3]=bhi.w;
            }
        }

        #pragma unroll
        for (int s = 0; s < 2; ++s) {
            uint4 af[4]; uint2 bf[4];
            #pragma unroll
            for (int mt = 0; mt < 4; ++mt)
                af[mt] = *(const uint4*)(Asl + (((s*8 + wm*4 + mt)*32 + lane) * 16));
            #pragma unroll
            for (int nt = 0; nt < 4; ++nt)
                bf[nt] = *(const uint2*)(Bsl + (((s*16 + wn*4 + nt)*32 + lane) * 8));
            #pragma unroll
            for (int mt = 0; mt < 4; ++mt)
                #pragma unroll
                for (int nt = 0; nt < 4; ++nt)
                    mma_f16(acc[mt][nt], af[mt].x, af[mt].z, af[mt].y, af[mt].w,
                            bf[nt].x, bf[nt].y);
        }
    }

    #pragma unroll
    for (int mt = 0; mt < 4; ++mt) {
        int m = m0 + wm*64 + mt*16 + (lane >> 2);
        #pragma unroll
        for (int nt = 0; nt < 4; ++nt) {
            int n = n0 + wn*32 + nt*8 + 2*(lane & 3);
            if (n < NQ) {
                *(float2*)&Tm[(size_t)m*NQ + n]     = make_float2(acc[mt][nt][0], acc[mt][nt][1]);
                *(float2*)&Tm[(size_t)(m+8)*NQ + n] = make_float2(acc[mt][nt][2], acc[mt][nt][3]);
            }
        }
    }
}

// ------------- gather epilogue + cosine-window blend -> output (2,128,80,80)
__global__ void k_combine(float* __restrict__ out) {
    int idx = blockIdx.x*blockDim.x + threadIdx.x;
    const int total = NB*NC*FH*FW;
    if (idx >= total) return;
    int X = idx % FW; int t = idx / FW;
    int Y = t % FH; t /= FH;
    int c = t % NC; int b = t / NC;

    int dys[2], hh[2]; int ny = 0;
    if ((Y & 1) == 0) {
        dys[ny] = 0; hh[ny] = Y >> 1; ny++;
        if (Y >= 2) { dys[ny] = 2; hh[ny] = (Y-2) >> 1; ny++; }
    } else {
        dys[ny] = 1; hh[ny] = (Y-1) >> 1; ny++;
        if (Y <= 2*HS - 3) { dys[ny] = -1; hh[ny] = (Y+1) >> 1; ny++; }
    }
    int dxs[2], ww[2]; int nx = 0;
    if ((X & 1) == 0) {
        dxs[nx] = 0; ww[nx] = X >> 1; nx++;
        if (X >= 2) { dxs[nx] = 2; ww[nx] = (X-2) >> 1; nx++; }
    } else {
        dxs[nx] = 1; ww[nx] = (X-1) >> 1; nx++;
        if (X <= 2*HS - 3) { dxs[nx] = -1; ww[nx] = (X+1) >> 1; nx++; }
    }

    const float PI = 3.14159265358979323846f;
    float wl = 0.5f*(1.f + cosf(PI * (float)X        / (float)(FW-1)));
    float wr = 0.5f*(1.f + cosf(PI * (float)(FW-1-X) / (float)(FW-1)));

    float res = 0.f;
    for (int s = 0; s < 2; ++s) {
        const float* T = g_T + (size_t)(b*2 + s)*MROWS*NQ;
        float acc = 0.f;
        for (int iy = 0; iy < ny; ++iy) {
            for (int ix = 0; ix < nx; ++ix) {
                int m = c*16 + (dys[iy]+1)*4 + (dxs[ix]+1);
                acc += T[(size_t)m*NQ + hh[iy]*HS + ww[ix]];
            }
        }
        res += (s == 0 ? wl : wr) * 0.25f * acc;
    }
    out[idx] = res;
}

// ------------------------------------------------------------------ launcher
extern "C" void kernel_launch(void* const* d_in, const int* in_sizes, int n_in,
                              void* d_out, int out_size) {
    const float* left      = (const float*)d_in[0];
    const float* right     = (const float*)d_in[1];
    const float* mid       = (const float*)d_in[2];
    const float* raw_left  = (const float*)d_in[3];
    const float* raw_right = (const float*)d_in[4];
    float* outp = (float*)d_out;

    cudaFuncSetAttribute(k_gemm2h, cudaFuncAttributeMaxDynamicSharedMemorySize, G2_SMEM);

    int t1 = NB*3*NC*NQ;
    k_downsample<<<(t1+255)/256, 256>>>(left, right, mid);
    k_cvt<<<dim3(NQ/32, NC/32, NB*3), dim3(32, 8)>>>();
    int t2 = NB*2*NQ;
    k_sumsq<<<(t2+127)/128, 128>>>();
    k_norm<<<(t2+127)/128, 128>>>();

    dim3 g1((NQ+127)/128, (NQ+127)/128, NB*2);   // 13 x 13 x 4
    k_gemm1h<<<g1, 256>>>();

    k_psAB<<<NB*2*HS*HS, 256>>>();               // fused passes A+B (6400 blocks)

    long long tp = (long long)NB*2*NQ*NQ;
    int nbElem = (int)((tp + 255) / 256);
    k_passC<<<nbElem, 256>>>();
    k_passD<<<nbElem, 256>>>();

    k_softmax_stats<<<dim3(NQ/64, NB*2), 256>>>();
    k_attnT<<<dim3(NQ/32, NQ/32, NB*2), dim3(32, 8)>>>();

    int tg8 = NB*2*MROWS*(NQ/8);
    k_buildG<<<(tg8+255)/256, 256>>>(raw_left, raw_right);

    dim3 g2(MROWS/128, (NQ+127)/128, NB*2);
    k_gemm2h<<<g2, 256, G2_SMEM>>>();

    int to = NB*NC*FH*FW;
    k_combine<<<(to+255)/256, 256>>>(outp);
}

// round 13
// speedup vs baseline: 1.2560x; 1.0583x over previous
#include <cuda_runtime.h>
#include <cuda_fp16.h>
#include <math.h>
#include <stdint.h>

// Problem constants
#define NB 2
#define NC 128
#define FH 80
#define FW 80
#define HS 40            // downsampled H=W
#define NQ 1600          // HS*HS
#define NEPS 0.1152f     // 1152 * EPS
#define SCL 10.0f
#define MROWS 2048       // NC * 16 offsets

// fp16 mma GEMM2 config
#define KT 32
#define G2_SMEM 32768

// Static scratch
__device__ float  g_ds[NB*3*NC*NQ];          // downsampled [b][img][c][q] (fp32)
__device__ __align__(16) __half g_dsh[NB*3*NQ*256];  // [b][img][q][hi(128)|lo(128)]
__device__ float  g_E[NB*2*NQ];
__device__ float  g_ninv[NB*2*NQ];
__device__ float  g_smax[NB*2*NQ];
__device__ float  g_sinv[NB*2*NQ];
__device__ float  g_bufA[NB*2*NQ*NQ];        // ping
__device__ float  g_bufB[NB*2*NQ*NQ];        // pong
__device__ __align__(16) __half g_Gh[NB*2*MROWS*NQ];
__device__ __align__(16) __half g_ATh[NB*2*NQ*NQ];
__device__ float  g_T[NB*2*MROWS*NQ];

// ---------------------------------------------------------------- downsample
__global__ void k_downsample(const float* __restrict__ left,
                             const float* __restrict__ right,
                             const float* __restrict__ mid) {
    int idx = blockIdx.x * blockDim.x + threadIdx.x;
    const int total = NB*3*NC*NQ;
    if (idx >= total) return;
    int q = idx % NQ;
    int t = idx / NQ;
    int c = t % NC; t /= NC;
    int img = t % 3; int b = t / 3;
    const float* src = (img == 0) ? left : (img == 1 ? right : mid);
    int qh = q / HS, qw = q % HS;
    g_ds[idx] = src[(size_t)((b*NC + c)*FH + 2*qh)*FW + 2*qw];
}

// ---------------- transpose-convert g_ds [c][q] -> g_dsh [q][hi|lo] (halves)
__global__ void k_cvt() {
    __shared__ float tile[32][33];
    int img = blockIdx.z;                    // b*3+img composite (0..5)
    int q0 = blockIdx.x * 32, c0 = blockIdx.y * 32;
    const float* __restrict__ src = g_ds + (size_t)img*NC*NQ;
    __half* __restrict__ dst = g_dsh + (size_t)img*NQ*256;
    int tx = threadIdx.x, ty = threadIdx.y;  // 32 x 8
    for (int r = ty; r < 32; r += 8)
        tile[r][tx] = src[(size_t)(c0+r)*NQ + q0 + tx];
    __syncthreads();
    for (int r = ty; r < 32; r += 8) {
        int q = q0 + r, c = c0 + tx;
        float v = tile[tx][r];
        __half hi = __float2half_rn(v);
        __half lo = __float2half_rn(v - __half2float(hi));
        dst[(size_t)q*256 + c]       = hi;
        dst[(size_t)q*256 + 128 + c] = lo;
    }
}

// ------------------------------------------------- channel sum-of-squares
__global__ void k_sumsq() {
    int idx = blockIdx.x*blockDim.x + threadIdx.x;
    const int total = NB*2*NQ;
    if (idx >= total) return;
    int q = idx % NQ; int t = idx / NQ;
    int s = t % 2; int b = t / 2;
    const float* p = g_ds + (size_t)(b*3 + s)*NC*NQ + q;
    float acc = 0.f;
    #pragma unroll 8
    for (int c = 0; c < NC; ++c) { float v = p[(size_t)c*NQ]; acc += v*v; }
    g_E[idx] = acc;
}

// -------------------------------------------------- patch norm
__global__ void k_norm() {
    int idx = blockIdx.x*blockDim.x + threadIdx.x;
    const int total = NB*2*NQ;
    if (idx >= total) return;
    int q = idx % NQ; int bs = idx / NQ;
    int qh = q/HS, qw = q%HS;
    float acc = NEPS;
    for (int di=-1; di<=1; ++di) {
        int h = qh+di; if (h < 0 || h >= HS) continue;
        for (int dj=-1; dj<=1; ++dj) {
            int w = qw+dj; if (w < 0 || w >= HS) continue;
            acc += g_E[bs*NQ + h*HS + w];
        }
    }
    g_ninv[idx] = rsqrtf(acc);
}

// ------------- shared fp16 mma helper
__device__ __forceinline__ void mma_f16(float* c, uint32_t a0, uint32_t a1,
                                        uint32_t a2, uint32_t a3,
                                        uint32_t b0, uint32_t b1) {
    asm volatile(
        "mma.sync.aligned.m16n8k16.row.col.f32.f16.f16.f32 "
        "{%0,%1,%2,%3}, {%4,%5,%6,%7}, {%8,%9}, {%0,%1,%2,%3};"
        : "+f"(c[0]), "+f"(c[1]), "+f"(c[2]), "+f"(c[3])
        : "r"(a0), "r"(a1), "r"(a2), "r"(a3), "r"(b0), "r"(b1));
}

// ------------- GEMM1 (split-fp16, 3 products = fp32-quality)
__global__ void __launch_bounds__(256) k_gemm1h() {
    __shared__ char smx[32768];   // Ahi 8K | Alo 8K | Bhi 8K | Blo 8K
    const int bs = blockIdx.z;
    const int b = bs >> 1, s = bs & 1;
    const __half* __restrict__ Aq = g_dsh + (size_t)(b*3 + s)*NQ*256;
    const __half* __restrict__ Bp = g_dsh + (size_t)(b*3 + 2)*NQ*256;
    float* __restrict__ Cout = g_bufA + (size_t)bs*NQ*NQ;
    const int m0 = blockIdx.x * 128, n0 = blockIdx.y * 128;
    const int t = threadIdx.x;
    const int lane = t & 31, wid = t >> 5;
    const int wm = wid & 1, wn = wid >> 1;

    const int prow = t >> 1, ps = t & 1;
    const int pmt = prow >> 4, prr = prow & 15;
    const int pgA = prr & 7;
    const int hwA = (prr >> 3) << 3;
    const int pnt = prow >> 3, pgB = prow & 7;
    const int rowA = (m0 + prow < NQ) ? (m0 + prow) : (NQ - 1);
    const int rowB = (n0 + prow < NQ) ? (n0 + prow) : (NQ - 1);

    char* Ahi = smx;
    char* Alo = smx + 8192;
    char* Bhi = smx + 16384;
    char* Blo = smx + 24576;

    float acc[4][4][4];
    #pragma unroll
    for (int i=0;i<4;i++)
        #pragma unroll
        for (int j=0;j<4;j++)
            #pragma unroll
            for (int k=0;k<4;k++) acc[i][j][k] = 0.f;

    for (int kt = 0; kt < 4; ++kt) {
        const int k0 = kt * KT;
        {
            const __half* abase = Aq + (size_t)rowA*256 + k0 + ps*16;
            const __half* bbase = Bp + (size_t)rowB*256 + k0 + ps*16;
            uint4 Ah0 = *(const uint4*)(abase);
            uint4 Ah1 = *(const uint4*)(abase + 8);
            uint4 Al0 = *(const uint4*)(abase + 128);
            uint4 Al1 = *(const uint4*)(abase + 136);
            uint4 Bh0 = *(const uint4*)(bbase);
            uint4 Bh1 = *(const uint4*)(bbase + 8);
            uint4 Bl0 = *(const uint4*)(bbase + 128);
            uint4 Bl1 = *(const uint4*)(bbase + 136);
            uint32_t l0[4], h0[4];
            char* aw; char* bw;
            l0[0]=Ah0.x; l0[1]=Ah0.y; l0[2]=Ah0.z; l0[3]=Ah0.w;
            h0[0]=Ah1.x; h0[1]=Ah1.y; h0[2]=Ah1.z; h0[3]=Ah1.w;
            aw = Ahi + ((ps*8 + pmt)*32 + pgA*4) * 16 + hwA;
            #pragma unroll
            for (int j = 0; j < 4; ++j)
                *(uint2*)(aw + j*16) = make_uint2(l0[j], h0[j]);
            l0[0]=Al0.x; l0[1]=Al0.y; l0[2]=Al0.z; l0[3]=Al0.w;
            h0[0]=Al1.x; h0[1]=Al1.y; h0[2]=Al1.z; h0[3]=Al1.w;
            aw = Alo + ((ps*8 + pmt)*32 + pgA*4) * 16 + hwA;
            #pragma unroll
            for (int j = 0; j < 4; ++j)
                *(uint2*)(aw + j*16) = make_uint2(l0[j], h0[j]);
            l0[0]=Bh0.x; l0[1]=Bh0.y; l0[2]=Bh0.z; l0[3]=Bh0.w;
            h0[0]=Bh1.x; h0[1]=Bh1.y; h0[2]=Bh1.z; h0[3]=Bh1.w;
            bw = Bhi + ((ps*16 + pnt)*32 + pgB*4) * 8;
            #pragma unroll
            for (int j = 0; j < 4; ++j)
                *(uint2*)(bw + j*8) = make_uint2(l0[j], h0[j]);
            l0[0]=Bl0.x; l0[1]=Bl0.y; l0[2]=Bl0.z; l0[3]=Bl0.w;
            h0[0]=Bl1.x; h0[1]=Bl1.y; h0[2]=Bl1.z; h0[3]=Bl1.w;
            bw = Blo + ((ps*16 + pnt)*32 + pgB*4) * 8;
            #pragma unroll
            for (int j = 0; j < 4; ++j)
                *(uint2*)(bw + j*8) = make_uint2(l0[j], h0[j]);
        }
        __syncthreads();

        #pragma unroll
        for (int ss = 0; ss < 2; ++ss) {
            uint4 afh[4], afl[4]; uint2 bfh[4], bfl[4];
            #pragma unroll
            for (int mt = 0; mt < 4; ++mt) {
                afh[mt] = *(const uint4*)(Ahi + (((ss*8 + wm*4 + mt)*32 + lane) * 16));
                afl[mt] = *(const uint4*)(Alo + (((ss*8 + wm*4 + mt)*32 + lane) * 16));
            }
            #pragma unroll
            for (int nt = 0; nt < 4; ++nt) {
                bfh[nt] = *(const uint2*)(Bhi + (((ss*16 + wn*4 + nt)*32 + lane) * 8));
                bfl[nt] = *(const uint2*)(Blo + (((ss*16 + wn*4 + nt)*32 + lane) * 8));
            }
            #pragma unroll
            for (int mt = 0; mt < 4; ++mt)
                #pragma unroll
                for (int nt = 0; nt < 4; ++nt) {
                    mma_f16(acc[mt][nt], afh[mt].x, afh[mt].z, afh[mt].y, afh[mt].w,
                            bfh[nt].x, bfh[nt].y);
                    mma_f16(acc[mt][nt], afh[mt].x, afh[mt].z, afh[mt].y, afh[mt].w,
                            bfl[nt].x, bfl[nt].y);
                    mma_f16(acc[mt][nt], afl[mt].x, afl[mt].z, afl[mt].y, afl[mt].w,
                            bfh[nt].x, bfh[nt].y);
                }
        }
        __syncthreads();
    }

    #pragma unroll
    for (int mt = 0; mt < 4; ++mt) {
        int m = m0 + wm*64 + mt*16 + (lane >> 2);
        #pragma unroll
        for (int nt = 0; nt < 4; ++nt) {
            int n = n0 + wn*32 + nt*8 + 2*(lane & 3);
            if (n < NQ) {
                if (m < NQ)
                    *(float2*)&Cout[(size_t)m*NQ + n] =
                        make_float2(acc[mt][nt][0], acc[mt][nt][1]);
                if (m + 8 < NQ)
                    *(float2*)&Cout[(size_t)(m+8)*NQ + n] =
                        make_float2(acc[mt][nt][2], acc[mt][nt][3]);
            }
        }
    }
}

// ---------- FUSED passes A+B (slab-tiled): bufA -> bufB
__global__ void __launch_bounds__(256) k_psAB() {
    __shared__ float sl[3][40][40];
    int blk = blockIdx.x;                 // bs*1600 + qh*40 + ph
    int ph = blk % HS; int t2 = blk / HS;
    int qh = t2 % HS; int bs = t2 / HS;
    const float* __restrict__ In = g_bufA + (size_t)bs*NQ*NQ;
    float* __restrict__ Out = g_bufB + (size_t)bs*NQ*NQ;
    const int tid = threadIdx.x;

    #pragma unroll
    for (int e = -1; e <= 1; ++e) {
        int Qh = qh + e, Ph = ph + e;
        if (Qh < 0 || Qh >= HS || Ph < 0 || Ph >= HS) continue;
        const float* base = In + (size_t)(Qh*HS)*NQ + Ph*HS;
        for (int i = tid; i < 400; i += 256) {
            int row = i / 10, c4 = (i % 10) * 4;
            *(float4*)&sl[e+1][row][c4] = *(const float4*)(base + (size_t)row*NQ + c4);
        }
    }
    __syncthreads();

    const float* __restrict__ ninv = g_ninv + bs*NQ;
    const bool em = (qh > 0)    && (ph > 0);
    const bool ez = true;
    const bool ep = (qh < HS-1) && (ph < HS-1);
    for (int i = tid; i < 1600; i += 256) {
        int qw = i / 40, pw = i % 40;
        bool dp = (qw < HS-1) && (pw < HS-1);
        bool dmm = (qw > 0) && (pw > 0);
        float acc = 0.f;
        #pragma unroll
        for (int eh = 0; eh < 3; ++eh) {
            bool ok = (eh == 0) ? em : ((eh == 1) ? ez : ep);
            if (!ok) continue;
            float s = sl[eh][qw][pw];
            if (dmm) s += sl[eh][qw-1][pw-1];
            if (dp)  s += sl[eh][qw+1][pw+1];
            acc += s;
        }
        Out[(size_t)(qh*HS + qw)*NQ + ph*HS + pw] = acc * ninv[qh*HS + qw];
    }
}

// ---------- pass C (fuse1, flat diag), DIAGONAL MARCHING: bufB -> bufA
// Thread computes 4 outputs (q0+i, p0+i) sharing 6 diagonal loads.
__global__ void k_passC() {
    int idx = blockIdx.x*blockDim.x + threadIdx.x;
    const int NP = NQ + 4;                 // p0 in [-3, NQ]
    const int total = NB*2*(NQ/4)*NP;
    if (idx >= total) return;
    int p0 = (idx % NP) - 3;
    int t = idx / NP;
    int qg = t % (NQ/4);
    int bs = t / (NQ/4);
    int q0 = qg * 4;
    const float* __restrict__ S = g_bufB + (size_t)bs*NQ*NQ;
    float* __restrict__ O = g_bufA + (size_t)bs*NQ*NQ;
    float diag[6];
    #pragma unroll
    for (int j = 0; j < 6; ++j) {
        int r = q0 - 1 + j, c = p0 - 1 + j;
        diag[j] = (r >= 0 && r < NQ && c >= 0 && c < NQ) ? S[(size_t)r*NQ + c] : 0.f;
    }
    #pragma unroll
    for (int i = 0; i < 4; ++i) {
        int q = q0 + i, p = p0 + i;
        if (p < 0 || p >= NQ) continue;
        float acc = diag[i+1];
        if (q > 0 && p > 0)       acc += diag[i];
        if (q < NQ-1 && p < NQ-1) acc += diag[i+2];
        O[(size_t)q*NQ + p] = acc;
    }
}

// ---------- pass D (fuse2), DIAGONAL MARCHING in (qh,ph): bufA -> bufB
// FIXED: ph0 decoupled from 4-alignment (ph0 in [-3,39]) so every (qh,ph)
// pair is covered exactly once (qh determines i = qh mod 4; ph0 = ph - i).
// Fast path: aligned 6-tap diagonal fully interior (qh0 in [4,32], ph0 in [1,34]).
__global__ void k_passD() {
    int idx = blockIdx.x*blockDim.x + threadIdx.x;
    const int NPH = HS + 3;                // ph0 in [-3, 39] -> 43 values
    const int total = NB*2*10*HS*NPH*HS;   // 2,752,000
    if (idx >= total) return;
    int pw = idx % HS; int t = idx / HS;
    int ph0 = (t % NPH) - 3; t /= NPH;
    int qw = t % HS; t /= HS;
    int qhg = t % 10; int bs = t / 10;
    const float* __restrict__ F = g_bufA + (size_t)bs*NQ*NQ;
    float* __restrict__ O = g_bufB + (size_t)bs*NQ*NQ;
    const int qh0 = qhg*4;
    if (qhg >= 1 && qhg <= 8 && ph0 >= 1 && ph0 <= 34) {
        float diag[6];
        #pragma unroll
        for (int j = 0; j < 6; ++j)
            diag[j] = F[(size_t)((qh0-1+j)*HS + qw)*NQ + (ph0-1+j)*HS + pw];
        #pragma unroll
        for (int i = 0; i < 4; ++i)
            O[(size_t)((qh0+i)*HS + qw)*NQ + (ph0+i)*HS + pw] =
                diag[i] + diag[i+1] + diag[i+2];
    } else {
        #pragma unroll
        for (int i = 0; i < 4; ++i) {
            int qh = qh0 + i, ph = ph0 + i;
            if (ph < 0 || ph >= HS) continue;
            int q = qh*HS + qw, p = ph*HS + pw;
            float acc = F[(size_t)q*NQ + p];
            if (q > 0 && p > 0) {
                int qm = (qh > 0) ? (q - HS) : ((HS-1)*HS + qw - 1);
                int pm = (ph > 0) ? (p - HS) : ((HS-1)*HS + pw - 1);
                acc += F[(size_t)qm*NQ + pm];
            }
            if (q < NQ-1 && p < NQ-1) {
                int qp = (qh < HS-1) ? (q + HS) : (qw + 1);
                int pp = (ph < HS-1) ? (p + HS) : (pw + 1);
                acc += F[(size_t)qp*NQ + pp];
            }
            O[(size_t)q*NQ + p] = acc;
        }
    }
}

// --------------- softmax stats, ONLINE single sweep (reads bufB)
__global__ void k_softmax_stats() {
    int bs = blockIdx.y;
    int p0 = blockIdx.x * 64;
    const float* __restrict__ F = g_bufB + (size_t)bs*NQ*NQ;
    int px = threadIdx.x & 63;
    int qy = threadIdx.x >> 6;        // 0..3
    int p = p0 + px;
    __shared__ float redm[4][64], reds[4][64];
    float mx = -3.4e38f, sm = 0.f;
    for (int q = qy; q < NQ; q += 4) {
        float v = F[(size_t)q*NQ + p];
        if (v <= mx) {
            sm += __expf(SCL * (v - mx));
        } else {
            sm = sm * __expf(SCL * (mx - v)) + 1.f;
            mx = v;
        }
    }
    redm[qy][px] = mx;
    reds[qy][px] = sm;
    __syncthreads();
    if (qy == 0) {
        float m0_ = redm[0][px], m1 = redm[1][px], m2 = redm[2][px], m3 = redm[3][px];
        float M = fmaxf(fmaxf(m0_, m1), fmaxf(m2, m3));
        float S = reds[0][px] * __expf(SCL * (m0_ - M))
                + reds[1][px] * __expf(SCL * (m1 - M))
                + reds[2][px] * __expf(SCL * (m2 - M))
                + reds[3][px] * __expf(SCL * (m3 - M));
        g_smax[bs*NQ + p] = M;
        g_sinv[bs*NQ + p] = 1.0f / S;
    }
}

// --------------- attnT: transposed, normalized attn as half (bufB -> g_ATh)
__global__ void k_attnT() {
    __shared__ float tile[32][33];
    int bs = blockIdx.z;
    int q0 = blockIdx.x * 32, p0 = blockIdx.y * 32;
    const float* __restrict__ F = g_bufB + (size_t)bs*NQ*NQ;
    __half* __restrict__ O = g_ATh + (size_t)bs*NQ*NQ;
    int tx = threadIdx.x, ty = threadIdx.y;  // 32 x 8
    for (int r = ty; r < 32; r += 8)
        tile[r][tx] = F[(size_t)(q0+r)*NQ + p0 + tx];
    __syncthreads();
    for (int r = ty; r < 32; r += 8) {
        int p = p0 + r;
        float e = __expf(SCL * (tile[tx][r] - g_smax[bs*NQ + p])) * g_sinv[bs*NQ + p];
        O[(size_t)p*NQ + q0 + tx] = __float2half_rn(e);
    }
}

// --------------- build paste operand G[bs][m][q] as half, 8 q per thread
__global__ void k_buildG(const float* __restrict__ raw_left,
                         const float* __restrict__ raw_right) {
    int idx = blockIdx.x*blockDim.x + threadIdx.x;
    const int total8 = NB*2*MROWS*(NQ/8);
    if (idx >= total8) return;
    int q8 = (idx % (NQ/8)) * 8;
    int t = idx / (NQ/8);
    int m = t % MROWS;
    int bs = t / MROWS;
    int b = bs >> 1, s = bs & 1;
    int c = m >> 4;
    int o = m & 15;
    int dy = (o >> 2) - 1, dx = (o & 3) - 1;
    int qh = q8 / HS, qw0 = q8 - (q8/HS)*HS;
    int y = 2*qh + dy;
    const float* raw = (s ? raw_right : raw_left) + (size_t)(b*NC + c)*FH*FW;
    __half hv[8];
    if (y >= 0 && y < FH) {
        const float* rrow = raw + (size_t)y*FW;
        #pragma unroll
        for (int j = 0; j < 8; ++j) {
            int x = 2*(qw0 + j) + dx;
            hv[j] = (x >= 0 && x < FW) ? __float2half_rn(rrow[x]) : __half(0.f);
        }
    } else {
        #pragma unroll
        for (int j = 0; j < 8; ++j) hv[j] = __half(0.f);
    }
    *(uint4*)&g_Gh[(size_t)(bs*MROWS + m)*NQ + q8] = *(uint4*)hv;
}

// ------------- GEMM2 (mma.sync fp16, f32 accum): T[m,p] = sum_q G[m,q] * attnT[p,q]
__global__ void __launch_bounds__(256) k_gemm2h() {
    extern __shared__ char smx[];
    const int bs = blockIdx.z;
    const __half* __restrict__ Gm = g_Gh  + (size_t)bs*MROWS*NQ;
    const __half* __restrict__ Bm = g_ATh + (size_t)bs*NQ*NQ;
    float* __restrict__ Tm = g_T + (size_t)bs*MROWS*NQ;
    const int m0 = blockIdx.x * 128, n0 = blockIdx.y * 128;
    const int t = threadIdx.x;
    const int lane = t & 31, wid = t >> 5;
    const int wm = wid & 1, wn = wid >> 1;

    const int prow = t >> 1, ps = t & 1;
    const int pmt = prow >> 4, prr = prow & 15;
    const int pgA = prr & 7;
    const int hwA = (prr >> 3) << 3;
    const int pnt = prow >> 3, pgB = prow & 7;
    const bool pBvalid = (n0 + prow) < NQ;

    uint32_t al[4], ah[4], bl[4], bh[4];

    float acc[4][4][4];
    #pragma unroll
    for (int i=0;i<4;i++)
        #pragma unroll
        for (int j=0;j<4;j++)
            #pragma unroll
            for (int k=0;k<4;k++) acc[i][j][k] = 0.f;

    {
        const uint4* pa = (const uint4*)(Gm + (size_t)(m0+prow)*NQ + ps*16);
        uint4 lo = pa[0], hi = pa[1];
        al[0]=lo.x; al[1]=lo.y; al[2]=lo.z; al[3]=lo.w;
        ah[0]=hi.x; ah[1]=hi.y; ah[2]=hi.z; ah[3]=hi.w;
        if (pBvalid) {
            const uint4* pb = (const uint4*)(Bm + (size_t)(n0+prow)*NQ + ps*16);
            uint4 blo = pb[0], bhi = pb[1];
            bl[0]=blo.x; bl[1]=blo.y; bl[2]=blo.z; bl[3]=blo.w;
            bh[0]=bhi.x; bh[1]=bhi.y; bh[2]=bhi.z; bh[3]=bhi.w;
        } else {
            #pragma unroll
            for (int j=0;j<4;j++) { bl[j]=0u; bh[j]=0u; }
        }
    }

    const int NTILES = NQ / KT;
    for (int it = 0; it < NTILES; ++it) {
        char* base = smx + (it & 1) * 16384;
        char* Asl = base;
        char* Bsl = base + 8192;

        {
            char* aw = Asl + ((ps*8 + pmt)*32 + pgA*4) * 16 + hwA;
            char* bw = Bsl + ((ps*16 + pnt)*32 + pgB*4) * 8;
            #pragma unroll
            for (int j = 0; j < 4; ++j) {
                *(uint2*)(aw + j*16) = make_uint2(al[j], ah[j]);
                *(uint2*)(bw + j*8)  = make_uint2(bl[j], bh[j]);
            }
        }
        __syncthreads();

        if (it + 1 < NTILES) {
            int k0n = (it + 1) * KT;
            const uint4* pa = (const uint4*)(Gm + (size_t)(m0+prow)*NQ + k0n + ps*16);
            uint4 lo = pa[0], hi = pa[1];
            al[0]=lo.x; al[1]=lo.y; al[2]=lo.z; al[3]=lo.w;
            ah[0]=hi.x; ah[1]=hi.y; ah[2]=hi.z; ah[3]=hi.w;
            if (pBvalid) {
                const uint4* pb = (const uint4*)(Bm + (size_t)(n0+prow)*NQ + k0n + ps*16);
                uint4 blo = pb[0], bhi = pb[1];
                bl[0]=blo.x; bl[1]=blo.y; bl[2]=blo.z; bl[3]=blo.w;
                bh[0]=bhi.x; bh[1]=bhi.y; bh[2]=bhi.z; bh[3]=bhi.w;
            }
        }

        #pragma unroll
        for (int s = 0; s < 2; ++s) {
            uint4 af[4]; uint2 bf[4];
            #pragma unroll
            for (int mt = 0; mt < 4; ++mt)
                af[mt] = *(const uint4*)(Asl + (((s*8 + wm*4 + mt)*32 + lane) * 16));
            #pragma unroll
            for (int nt = 0; nt < 4; ++nt)
                bf[nt] = *(const uint2*)(Bsl + (((s*16 + wn*4 + nt)*32 + lane) * 8));
            #pragma unroll
            for (int mt = 0; mt < 4; ++mt)
                #pragma unroll
                for (int nt = 0; nt < 4; ++nt)
                    mma_f16(acc[mt][nt], af[mt].x, af[mt].z, af[mt].y, af[mt].w,
                            bf[nt].x, bf[nt].y);
        }
    }

    #pragma unroll
    for (int mt = 0; mt < 4; ++mt) {
        int m = m0 + wm*64 + mt*16 + (lane >> 2);
        #pragma unroll
        for (int nt = 0; nt < 4; ++nt) {
            int n = n0 + wn*32 + nt*8 + 2*(lane & 3);
            if (n < NQ) {
                *(float2*)&Tm[(size_t)m*NQ + n]     = make_float2(acc[mt][nt][0], acc[mt][nt][1]);
                *(float2*)&Tm[(size_t)(m+8)*NQ + n] = make_float2(acc[mt][nt][2], acc[mt][nt][3]);
            }
        }
    }
}

// ------------- gather epilogue + cosine-window blend -> output (2,128,80,80)
__global__ void k_combine(float* __restrict__ out) {
    int idx = blockIdx.x*blockDim.x + threadIdx.x;
    const int total = NB*NC*FH*FW;
    if (idx >= total) return;
    int X = idx % FW; int t = idx / FW;
    int Y = t % FH; t /= FH;
    int c = t % NC; int b = t / NC;

    int dys[2], hh[2]; int ny = 0;
    if ((Y & 1) == 0) {
        dys[ny] = 0; hh[ny] = Y >> 1; ny++;
        if (Y >= 2) { dys[ny] = 2; hh[ny] = (Y-2) >> 1; ny++; }
    } else {
        dys[ny] = 1; hh[ny] = (Y-1) >> 1; ny++;
        if (Y <= 2*HS - 3) { dys[ny] = -1; hh[ny] = (Y+1) >> 1; ny++; }
    }
    int dxs[2], ww[2]; int nx = 0;
    if ((X & 1) == 0) {
        dxs[nx] = 0; ww[nx] = X >> 1; nx++;
        if (X >= 2) { dxs[nx] = 2; ww[nx] = (X-2) >> 1; nx++; }
    } else {
        dxs[nx] = 1; ww[nx] = (X-1) >> 1; nx++;
        if (X <= 2*HS - 3) { dxs[nx] = -1; ww[nx] = (X+1) >> 1; nx++; }
    }

    const float PI = 3.14159265358979323846f;
    float wl = 0.5f*(1.f + cosf(PI * (float)X        / (float)(FW-1)));
    float wr = 0.5f*(1.f + cosf(PI * (float)(FW-1-X) / (float)(FW-1)));

    float res = 0.f;
    for (int s = 0; s < 2; ++s) {
        const float* T = g_T + (size_t)(b*2 + s)*MROWS*NQ;
        float acc = 0.f;
        for (int iy = 0; iy < ny; ++iy) {
            for (int ix = 0; ix < nx; ++ix) {
                int m = c*16 + (dys[iy]+1)*4 + (dxs[ix]+1);
                acc += T[(size_t)m*NQ + hh[iy]*HS + ww[ix]];
            }
        }
        res += (s == 0 ? wl : wr) * 0.25f * acc;
    }
    out[idx] = res;
}

// ------------------------------------------------------------------ launcher
extern "C" void kernel_launch(void* const* d_in, const int* in_sizes, int n_in,
                              void* d_out, int out_size) {
    const float* left      = (const float*)d_in[0];
    const float* right     = (const float*)d_in[1];
    const float* mid       = (const float*)d_in[2];
    const float* raw_left  = (const float*)d_in[3];
    const float* raw_right = (const float*)d_in[4];
    float* outp = (float*)d_out;

    cudaFuncSetAttribute(k_gemm2h, cudaFuncAttributeMaxDynamicSharedMemorySize, G2_SMEM);

    int t1 = NB*3*NC*NQ;
    k_downsample<<<(t1+255)/256, 256>>>(left, right, mid);
    k_cvt<<<dim3(NQ/32, NC/32, NB*3), dim3(32, 8)>>>();
    int t2 = NB*2*NQ;
    k_sumsq<<<(t2+127)/128, 128>>>();
    k_norm<<<(t2+127)/128, 128>>>();

    dim3 g1((NQ+127)/128, (NQ+127)/128, NB*2);   // 13 x 13 x 4
    k_gemm1h<<<g1, 256>>>();

    k_psAB<<<NB*2*HS*HS, 256>>>();               // fused passes A+B

    int tC = NB*2*(NQ/4)*(NQ+4);
    k_passC<<<(tC+255)/256, 256>>>();

    int tD = NB*2*10*HS*(HS+3)*HS;
    k_passD<<<(tD+255)/256, 256>>>();

    k_softmax_stats<<<dim3(NQ/64, NB*2), 256>>>();
    k_attnT<<<dim3(NQ/32, NQ/32, NB*2), dim3(32, 8)>>>();

    int tg8 = NB*2*MROWS*(NQ/8);
    k_buildG<<<(tg8+255)/256, 256>>>(raw_left, raw_right);

    dim3 g2(MROWS/128, (NQ+127)/128, NB*2);
    k_gemm2h<<<g2, 256, G2_SMEM>>>();

    int to = NB*NC*FH*FW;
    k_combine<<<(to+255)/256, 256>>>(outp);
}

// round 14
// speedup vs baseline: 1.2850x; 1.0231x over previous
#include <cuda_runtime.h>
#include <cuda_fp16.h>
#include <math.h>
#include <stdint.h>

// Problem constants
#define NB 2
#define NC 128
#define FH 80
#define FW 80
#define HS 40            // downsampled H=W
#define NQ 1600          // HS*HS
#define NEPS 0.1152f     // 1152 * EPS
#define SCL 10.0f
#define MROWS 2048       // NC * 16 offsets

// fp16 mma GEMM configs
#define KT 32
#define G2_SMEM 49152    // 2 buffers x (16KB A + 8KB B)

// Static scratch
__device__ float  g_ds[NB*3*NC*NQ];          // downsampled [b][img][c][q] (fp32)
__device__ __align__(16) __half g_dsh[NB*3*NQ*256];  // [b][img][q][hi(128)|lo(128)]
__device__ float  g_E[NB*2*NQ];
__device__ float  g_ninv[NB*2*NQ];
__device__ float  g_smax[NB*2*NQ];
__device__ float  g_sinv[NB*2*NQ];
__device__ float  g_bufA[NB*2*NQ*NQ];        // ping
__device__ float  g_bufB[NB*2*NQ*NQ];        // pong
__device__ __align__(16) __half g_Gh[NB*2*MROWS*NQ];
__device__ __align__(16) __half g_ATh[NB*2*NQ*NQ];
__device__ float  g_T[NB*2*MROWS*NQ];

// ---------------------------------------------------------------- downsample
__global__ void k_downsample(const float* __restrict__ left,
                             const float* __restrict__ right,
                             const float* __restrict__ mid) {
    int idx = blockIdx.x * blockDim.x + threadIdx.x;
    const int total = NB*3*NC*NQ;
    if (idx >= total) return;
    int q = idx % NQ;
    int t = idx / NQ;
    int c = t % NC; t /= NC;
    int img = t % 3; int b = t / 3;
    const float* src = (img == 0) ? left : (img == 1 ? right : mid);
    int qh = q / HS, qw = q % HS;
    g_ds[idx] = src[(size_t)((b*NC + c)*FH + 2*qh)*FW + 2*qw];
}

// ---------------- transpose-convert g_ds [c][q] -> g_dsh [q][hi|lo] (halves)
__global__ void k_cvt() {
    __shared__ float tile[32][33];
    int img = blockIdx.z;                    // b*3+img composite (0..5)
    int q0 = blockIdx.x * 32, c0 = blockIdx.y * 32;
    const float* __restrict__ src = g_ds + (size_t)img*NC*NQ;
    __half* __restrict__ dst = g_dsh + (size_t)img*NQ*256;
    int tx = threadIdx.x, ty = threadIdx.y;  // 32 x 8
    for (int r = ty; r < 32; r += 8)
        tile[r][tx] = src[(size_t)(c0+r)*NQ + q0 + tx];
    __syncthreads();
    for (int r = ty; r < 32; r += 8) {
        int q = q0 + r, c = c0 + tx;
        float v = tile[tx][r];
        __half hi = __float2half_rn(v);
        __half lo = __float2half_rn(v - __half2float(hi));
        dst[(size_t)q*256 + c]       = hi;
        dst[(size_t)q*256 + 128 + c] = lo;
    }
}

// ------------------------------------------------- channel sum-of-squares
__global__ void k_sumsq() {
    int idx = blockIdx.x*blockDim.x + threadIdx.x;
    const int total = NB*2*NQ;
    if (idx >= total) return;
    int q = idx % NQ; int t = idx / NQ;
    int s = t % 2; int b = t / 2;
    const float* p = g_ds + (size_t)(b*3 + s)*NC*NQ + q;
    float acc = 0.f;
    #pragma unroll 8
    for (int c = 0; c < NC; ++c) { float v = p[(size_t)c*NQ]; acc += v*v; }
    g_E[idx] = acc;
}

// -------------------------------------------------- patch norm
__global__ void k_norm() {
    int idx = blockIdx.x*blockDim.x + threadIdx.x;
    const int total = NB*2*NQ;
    if (idx >= total) return;
    int q = idx % NQ; int bs = idx / NQ;
    int qh = q/HS, qw = q%HS;
    float acc = NEPS;
    for (int di=-1; di<=1; ++di) {
        int h = qh+di; if (h < 0 || h >= HS) continue;
        for (int dj=-1; dj<=1; ++dj) {
            int w = qw+dj; if (w < 0 || w >= HS) continue;
            acc += g_E[bs*NQ + h*HS + w];
        }
    }
    g_ninv[idx] = rsqrtf(acc);
}

// ------------- shared fp16 mma helper
__device__ __forceinline__ void mma_f16(float* c, uint32_t a0, uint32_t a1,
                                        uint32_t a2, uint32_t a3,
                                        uint32_t b0, uint32_t b1) {
    asm volatile(
        "mma.sync.aligned.m16n8k16.row.col.f32.f16.f16.f32 "
        "{%0,%1,%2,%3}, {%4,%5,%6,%7}, {%8,%9}, {%0,%1,%2,%3};"
        : "+f"(c[0]), "+f"(c[1]), "+f"(c[2]), "+f"(c[3])
        : "r"(a0), "r"(a1), "r"(a2), "r"(a3), "r"(b0), "r"(b1));
}

// ------------- GEMM1 (split-fp16, 3 products = fp32-quality)
__global__ void __launch_bounds__(256) k_gemm1h() {
    __shared__ char smx[32768];   // Ahi 8K | Alo 8K | Bhi 8K | Blo 8K
    const int bs = blockIdx.z;
    const int b = bs >> 1, s = bs & 1;
    const __half* __restrict__ Aq = g_dsh + (size_t)(b*3 + s)*NQ*256;
    const __half* __restrict__ Bp = g_dsh + (size_t)(b*3 + 2)*NQ*256;
    float* __restrict__ Cout = g_bufA + (size_t)bs*NQ*NQ;
    const int m0 = blockIdx.x * 128, n0 = blockIdx.y * 128;
    const int t = threadIdx.x;
    const int lane = t & 31, wid = t >> 5;
    const int wm = wid & 1, wn = wid >> 1;

    const int prow = t >> 1, ps = t & 1;
    const int pmt = prow >> 4, prr = prow & 15;
    const int pgA = prr & 7;
    const int hwA = (prr >> 3) << 3;
    const int pnt = prow >> 3, pgB = prow & 7;
    const int rowA = (m0 + prow < NQ) ? (m0 + prow) : (NQ - 1);
    const int rowB = (n0 + prow < NQ) ? (n0 + prow) : (NQ - 1);

    char* Ahi = smx;
    char* Alo = smx + 8192;
    char* Bhi = smx + 16384;
    char* Blo = smx + 24576;

    float acc[4][4][4];
    #pragma unroll
    for (int i=0;i<4;i++)
        #pragma unroll
        for (int j=0;j<4;j++)
            #pragma unroll
            for (int k=0;k<4;k++) acc[i][j][k] = 0.f;

    for (int kt = 0; kt < 4; ++kt) {
        const int k0 = kt * KT;
        {
            const __half* abase = Aq + (size_t)rowA*256 + k0 + ps*16;
            const __half* bbase = Bp + (size_t)rowB*256 + k0 + ps*16;
            uint4 Ah0 = *(const uint4*)(abase);
            uint4 Ah1 = *(const uint4*)(abase + 8);
            uint4 Al0 = *(const uint4*)(abase + 128);
            uint4 Al1 = *(const uint4*)(abase + 136);
            uint4 Bh0 = *(const uint4*)(bbase);
            uint4 Bh1 = *(const uint4*)(bbase + 8);
            uint4 Bl0 = *(const uint4*)(bbase + 128);
            uint4 Bl1 = *(const uint4*)(bbase + 136);
            uint32_t l0[4], h0[4];
            char* aw; char* bw;
            l0[0]=Ah0.x; l0[1]=Ah0.y; l0[2]=Ah0.z; l0[3]=Ah0.w;
            h0[0]=Ah1.x; h0[1]=Ah1.y; h0[2]=Ah1.z; h0[3]=Ah1.w;
            aw = Ahi + ((ps*8 + pmt)*32 + pgA*4) * 16 + hwA;
            #pragma unroll
            for (int j = 0; j < 4; ++j)
                *(uint2*)(aw + j*16) = make_uint2(l0[j], h0[j]);
            l0[0]=Al0.x; l0[1]=Al0.y; l0[2]=Al0.z; l0[3]=Al0.w;
            h0[0]=Al1.x; h0[1]=Al1.y; h0[2]=Al1.z; h0[3]=Al1.w;
            aw = Alo + ((ps*8 + pmt)*32 + pgA*4) * 16 + hwA;
            #pragma unroll
            for (int j = 0; j < 4; ++j)
                *(uint2*)(aw + j*16) = make_uint2(l0[j], h0[j]);
            l0[0]=Bh0.x; l0[1]=Bh0.y; l0[2]=Bh0.z; l0[3]=Bh0.w;
            h0[0]=Bh1.x; h0[1]=Bh1.y; h0[2]=Bh1.z; h0[3]=Bh1.w;
            bw = Bhi + ((ps*16 + pnt)*32 + pgB*4) * 8;
            #pragma unroll
            for (int j = 0; j < 4; ++j)
                *(uint2*)(bw + j*8) = make_uint2(l0[j], h0[j]);
            l0[0]=Bl0.x; l0[1]=Bl0.y; l0[2]=Bl0.z; l0[3]=Bl0.w;
            h0[0]=Bl1.x; h0[1]=Bl1.y; h0[2]=Bl1.z; h0[3]=Bl1.w;
            bw = Blo + ((ps*16 + pnt)*32 + pgB*4) * 8;
            #pragma unroll
            for (int j = 0; j < 4; ++j)
                *(uint2*)(bw + j*8) = make_uint2(l0[j], h0[j]);
        }
        __syncthreads();

        #pragma unroll
        for (int ss = 0; ss < 2; ++ss) {
            uint4 afh[4], afl[4]; uint2 bfh[4], bfl[4];
            #pragma unroll
            for (int mt = 0; mt < 4; ++mt) {
                afh[mt] = *(const uint4*)(Ahi + (((ss*8 + wm*4 + mt)*32 + lane) * 16));
                afl[mt] = *(const uint4*)(Alo + (((ss*8 + wm*4 + mt)*32 + lane) * 16));
            }
            #pragma unroll
            for (int nt = 0; nt < 4; ++nt) {
                bfh[nt] = *(const uint2*)(Bhi + (((ss*16 + wn*4 + nt)*32 + lane) * 8));
                bfl[nt] = *(const uint2*)(Blo + (((ss*16 + wn*4 + nt)*32 + lane) * 8));
            }
            #pragma unroll
            for (int mt = 0; mt < 4; ++mt)
                #pragma unroll
                for (int nt = 0; nt < 4; ++nt) {
                    mma_f16(acc[mt][nt], afh[mt].x, afh[mt].z, afh[mt].y, afh[mt].w,
                            bfh[nt].x, bfh[nt].y);
                    mma_f16(acc[mt][nt], afh[mt].x, afh[mt].z, afh[mt].y, afh[mt].w,
                            bfl[nt].x, bfl[nt].y);
                    mma_f16(acc[mt][nt], afl[mt].x, afl[mt].z, afl[mt].y, afl[mt].w,
                            bfh[nt].x, bfh[nt].y);
                }
        }
        __syncthreads();
    }

    #pragma unroll
    for (int mt = 0; mt < 4; ++mt) {
        int m = m0 + wm*64 + mt*16 + (lane >> 2);
        #pragma unroll
        for (int nt = 0; nt < 4; ++nt) {
            int n = n0 + wn*32 + nt*8 + 2*(lane & 3);
            if (n < NQ) {
                if (m < NQ)
                    *(float2*)&Cout[(size_t)m*NQ + n] =
                        make_float2(acc[mt][nt][0], acc[mt][nt][1]);
                if (m + 8 < NQ)
                    *(float2*)&Cout[(size_t)(m+8)*NQ + n] =
                        make_float2(acc[mt][nt][2], acc[mt][nt][3]);
            }
        }
    }
}

// ---------- FUSED passes A+B (slab-tiled): bufA -> bufB
__global__ void __launch_bounds__(256) k_psAB() {
    __shared__ float sl[3][40][40];
    int blk = blockIdx.x;                 // bs*1600 + qh*40 + ph
    int ph = blk % HS; int t2 = blk / HS;
    int qh = t2 % HS; int bs = t2 / HS;
    const float* __restrict__ In = g_bufA + (size_t)bs*NQ*NQ;
    float* __restrict__ Out = g_bufB + (size_t)bs*NQ*NQ;
    const int tid = threadIdx.x;

    #pragma unroll
    for (int e = -1; e <= 1; ++e) {
        int Qh = qh + e, Ph = ph + e;
        if (Qh < 0 || Qh >= HS || Ph < 0 || Ph >= HS) continue;
        const float* base = In + (size_t)(Qh*HS)*NQ + Ph*HS;
        for (int i = tid; i < 400; i += 256) {
            int row = i / 10, c4 = (i % 10) * 4;
            *(float4*)&sl[e+1][row][c4] = *(const float4*)(base + (size_t)row*NQ + c4);
        }
    }
    __syncthreads();

    const float* __restrict__ ninv = g_ninv + bs*NQ;
    const bool em = (qh > 0)    && (ph > 0);
    const bool ez = true;
    const bool ep = (qh < HS-1) && (ph < HS-1);
    for (int i = tid; i < 1600; i += 256) {
        int qw = i / 40, pw = i % 40;
        bool dp = (qw < HS-1) && (pw < HS-1);
        bool dmm = (qw > 0) && (pw > 0);
        float acc = 0.f;
        #pragma unroll
        for (int eh = 0; eh < 3; ++eh) {
            bool ok = (eh == 0) ? em : ((eh == 1) ? ez : ep);
            if (!ok) continue;
            float s = sl[eh][qw][pw];
            if (dmm) s += sl[eh][qw-1][pw-1];
            if (dp)  s += sl[eh][qw+1][pw+1];
            acc += s;
        }
        Out[(size_t)(qh*HS + qw)*NQ + ph*HS + pw] = acc * ninv[qh*HS + qw];
    }
}

// ---------- pass C (fuse1, flat diag), DIAGONAL MARCHING: bufB -> bufA
__global__ void k_passC() {
    int idx = blockIdx.x*blockDim.x + threadIdx.x;
    const int NP = NQ + 4;                 // p0 in [-3, NQ]
    const int total = NB*2*(NQ/4)*NP;
    if (idx >= total) return;
    int p0 = (idx % NP) - 3;
    int t = idx / NP;
    int qg = t % (NQ/4);
    int bs = t / (NQ/4);
    int q0 = qg * 4;
    const float* __restrict__ S = g_bufB + (size_t)bs*NQ*NQ;
    float* __restrict__ O = g_bufA + (size_t)bs*NQ*NQ;
    float diag[6];
    #pragma unroll
    for (int j = 0; j < 6; ++j) {
        int r = q0 - 1 + j, c = p0 - 1 + j;
        diag[j] = (r >= 0 && r < NQ && c >= 0 && c < NQ) ? S[(size_t)r*NQ + c] : 0.f;
    }
    #pragma unroll
    for (int i = 0; i < 4; ++i) {
        int q = q0 + i, p = p0 + i;
        if (p < 0 || p >= NQ) continue;
        float acc = diag[i+1];
        if (q > 0 && p > 0)       acc += diag[i];
        if (q < NQ-1 && p < NQ-1) acc += diag[i+2];
        O[(size_t)q*NQ + p] = acc;
    }
}

// ---------- pass D (fuse2), DIAGONAL MARCHING in (qh,ph): bufA -> bufB
__global__ void k_passD() {
    int idx = blockIdx.x*blockDim.x + threadIdx.x;
    const int NPH = HS + 3;                // ph0 in [-3, 39] -> 43 values
    const int total = NB*2*10*HS*NPH*HS;   // 2,752,000
    if (idx >= total) return;
    int pw = idx % HS; int t = idx / HS;
    int ph0 = (t % NPH) - 3; t /= NPH;
    int qw = t % HS; t /= HS;
    int qhg = t % 10; int bs = t / 10;
    const float* __restrict__ F = g_bufA + (size_t)bs*NQ*NQ;
    float* __restrict__ O = g_bufB + (size_t)bs*NQ*NQ;
    const int qh0 = qhg*4;
    if (qhg >= 1 && qhg <= 8 && ph0 >= 1 && ph0 <= 34) {
        float diag[6];
        #pragma unroll
        for (int j = 0; j < 6; ++j)
            diag[j] = F[(size_t)((qh0-1+j)*HS + qw)*NQ + (ph0-1+j)*HS + pw];
        #pragma unroll
        for (int i = 0; i < 4; ++i)
            O[(size_t)((qh0+i)*HS + qw)*NQ + (ph0+i)*HS + pw] =
                diag[i] + diag[i+1] + diag[i+2];
    } else {
        #pragma unroll
        for (int i = 0; i < 4; ++i) {
            int qh = qh0 + i, ph = ph0 + i;
            if (ph < 0 || ph >= HS) continue;
            int q = qh*HS + qw, p = ph*HS + pw;
            float acc = F[(size_t)q*NQ + p];
            if (q > 0 && p > 0) {
                int qm = (qh > 0) ? (q - HS) : ((HS-1)*HS + qw - 1);
                int pm = (ph > 0) ? (p - HS) : ((HS-1)*HS + pw - 1);
                acc += F[(size_t)qm*NQ + pm];
            }
            if (q < NQ-1 && p < NQ-1) {
                int qp = (qh < HS-1) ? (q + HS) : (qw + 1);
                int pp = (ph < HS-1) ? (p + HS) : (pw + 1);
                acc += F[(size_t)qp*NQ + pp];
            }
            O[(size_t)q*NQ + p] = acc;
        }
    }
}

// --------------- softmax stats, ONLINE single sweep (reads bufB)
__global__ void k_softmax_stats() {
    int bs = blockIdx.y;
    int p0 = blockIdx.x * 64;
    const float* __restrict__ F = g_bufB + (size_t)bs*NQ*NQ;
    int px = threadIdx.x & 63;
    int qy = threadIdx.x >> 6;        // 0..3
    int p = p0 + px;
    __shared__ float redm[4][64], reds[4][64];
    float mx = -3.4e38f, sm = 0.f;
    for (int q = qy; q < NQ; q += 4) {
        float v = F[(size_t)q*NQ + p];
        if (v <= mx) {
            sm += __expf(SCL * (v - mx));
        } else {
            sm = sm * __expf(SCL * (mx - v)) + 1.f;
            mx = v;
        }
    }
    redm[qy][px] = mx;
    reds[qy][px] = sm;
    __syncthreads();
    if (qy == 0) {
        float m0_ = redm[0][px], m1 = redm[1][px], m2 = redm[2][px], m3 = redm[3][px];
        float M = fmaxf(fmaxf(m0_, m1), fmaxf(m2, m3));
        float S = reds[0][px] * __expf(SCL * (m0_ - M))
                + reds[1][px] * __expf(SCL * (m1 - M))
                + reds[2][px] * __expf(SCL * (m2 - M))
                + reds[3][px] * __expf(SCL * (m3 - M));
        g_smax[bs*NQ + p] = M;
        g_sinv[bs*NQ + p] = 1.0f / S;
    }
}

// --------------- attnT: transposed, normalized attn as half (bufB -> g_ATh)
__global__ void k_attnT() {
    __shared__ float tile[32][33];
    int bs = blockIdx.z;
    int q0 = blockIdx.x * 32, p0 = blockIdx.y * 32;
    const float* __restrict__ F = g_bufB + (size_t)bs*NQ*NQ;
    __half* __restrict__ O = g_ATh + (size_t)bs*NQ*NQ;
    int tx = threadIdx.x, ty = threadIdx.y;  // 32 x 8
    for (int r = ty; r < 32; r += 8)
        tile[r][tx] = F[(size_t)(q0+r)*NQ + p0 + tx];
    __syncthreads();
    for (int r = ty; r < 32; r += 8) {
        int p = p0 + r;
        float e = __expf(SCL * (tile[tx][r] - g_smax[bs*NQ + p])) * g_sinv[bs*NQ + p];
        O[(size_t)p*NQ + q0 + tx] = __float2half_rn(e);
    }
}

// --------------- build paste operand G[bs][m][q] as half, 8 q per thread
__global__ void k_buildG(const float* __restrict__ raw_left,
                         const float* __restrict__ raw_right) {
    int idx = blockIdx.x*blockDim.x + threadIdx.x;
    const int total8 = NB*2*MROWS*(NQ/8);
    if (idx >= total8) return;
    int q8 = (idx % (NQ/8)) * 8;
    int t = idx / (NQ/8);
    int m = t % MROWS;
    int bs = t / MROWS;
    int b = bs >> 1, s = bs & 1;
    int c = m >> 4;
    int o = m & 15;
    int dy = (o >> 2) - 1, dx = (o & 3) - 1;
    int qh = q8 / HS, qw0 = q8 - (q8/HS)*HS;
    int y = 2*qh + dy;
    const float* raw = (s ? raw_right : raw_left) + (size_t)(b*NC + c)*FH*FW;
    __half hv[8];
    if (y >= 0 && y < FH) {
        const float* rrow = raw + (size_t)y*FW;
        #pragma unroll
        for (int j = 0; j < 8; ++j) {
            int x = 2*(qw0 + j) + dx;
            hv[j] = (x >= 0 && x < FW) ? __float2half_rn(rrow[x]) : __half(0.f);
        }
    } else {
        #pragma unroll
        for (int j = 0; j < 8; ++j) hv[j] = __half(0.f);
    }
    *(uint4*)&g_Gh[(size_t)(bs*MROWS + m)*NQ + q8] = *(uint4*)hv;
}

// ------------- GEMM2 (mma.sync fp16, f32 accum): T[m,p] = sum_q G[m,q] * attnT[p,q]
// CTA tile 256(m) x 128(n), 512 threads (16 warps: 4m x 4n), warp tile 64x32.
// Halves B-operand L2 traffic vs the 128x128 tiling.
__global__ void __launch_bounds__(512) k_gemm2h() {
    extern __shared__ char smx[];
    const int bs = blockIdx.z;
    const __half* __restrict__ Gm = g_Gh  + (size_t)bs*MROWS*NQ;
    const __half* __restrict__ Bm = g_ATh + (size_t)bs*NQ*NQ;
    float* __restrict__ Tm = g_T + (size_t)bs*MROWS*NQ;
    const int m0 = blockIdx.x * 256, n0 = blockIdx.y * 128;
    const int t = threadIdx.x;
    const int lane = t & 31, wid = t >> 5;
    const int wm = wid & 3, wn = wid >> 2;      // warp grid 4(m) x 4(n)

    // A producer: 256 rows x 2 k-chunks = 512 assignments (all threads)
    const int aRow = t >> 1, psA = t & 1;
    const int aMg = aRow >> 4, aRr = aRow & 15;
    const int aPg = aRr & 7;
    const int aHw = (aRr >> 3) << 3;
    // B producer: 128 rows x 2 k-chunks = 256 assignments (threads < 256)
    const bool hasB = (t < 256);
    const int bRow = t >> 1;                     // valid when hasB
    const int psB = t & 1;
    const int bNg = bRow >> 3, bPg = bRow & 7;
    const bool pBvalid = hasB && ((n0 + bRow) < NQ);

    uint32_t al[4], ah[4], bl[4], bh[4];

    float acc[4][4][4];
    #pragma unroll
    for (int i=0;i<4;i++)
        #pragma unroll
        for (int j=0;j<4;j++)
            #pragma unroll
            for (int k=0;k<4;k++) acc[i][j][k] = 0.f;

    // prime tile 0
    {
        const uint4* pa = (const uint4*)(Gm + (size_t)(m0+aRow)*NQ + psA*16);
        uint4 lo = pa[0], hi = pa[1];
        al[0]=lo.x; al[1]=lo.y; al[2]=lo.z; al[3]=lo.w;
        ah[0]=hi.x; ah[1]=hi.y; ah[2]=hi.z; ah[3]=hi.w;
        if (pBvalid) {
            const uint4* pb = (const uint4*)(Bm + (size_t)(n0+bRow)*NQ + psB*16);
            uint4 blo = pb[0], bhi = pb[1];
            bl[0]=blo.x; bl[1]=blo.y; bl[2]=blo.z; bl[3]=blo.w;
            bh[0]=bhi.x; bh[1]=bhi.y; bh[2]=bhi.z; bh[3]=bhi.w;
        } else {
            #pragma unroll
            for (int j=0;j<4;j++) { bl[j]=0u; bh[j]=0u; }
        }
    }

    const int NTILES = NQ / KT;
    for (int it = 0; it < NTILES; ++it) {
        char* base = smx + (it & 1) * 24576;
        char* Asl = base;             // 2 ks x 16 groups x 32 slots x 16B = 16KB
        char* Bsl = base + 16384;     // 2 ks x 16 groups x 32 slots x 8B  = 8KB

        {
            char* aw = Asl + ((psA*16 + aMg)*32 + aPg*4) * 16 + aHw;
            #pragma unroll
            for (int j = 0; j < 4; ++j)
                *(uint2*)(aw + j*16) = make_uint2(al[j], ah[j]);
            if (hasB) {
                char* bw = Bsl + ((psB*16 + bNg)*32 + bPg*4) * 8;
                #pragma unroll
                for (int j = 0; j < 4; ++j)
                    *(uint2*)(bw + j*8)  = make_uint2(bl[j], bh[j]);
            }
        }
        __syncthreads();

        if (it + 1 < NTILES) {
            int k0n = (it + 1) * KT;
            const uint4* pa = (const uint4*)(Gm + (size_t)(m0+aRow)*NQ + k0n + psA*16);
            uint4 lo = pa[0], hi = pa[1];
            al[0]=lo.x; al[1]=lo.y; al[2]=lo.z; al[3]=lo.w;
            ah[0]=hi.x; ah[1]=hi.y; ah[2]=hi.z; ah[3]=hi.w;
            if (pBvalid) {
                const uint4* pb = (const uint4*)(Bm + (size_t)(n0+bRow)*NQ + k0n + psB*16);
                uint4 blo = pb[0], bhi = pb[1];
                bl[0]=blo.x; bl[1]=blo.y; bl[2]=blo.z; bl[3]=blo.w;
                bh[0]=bhi.x; bh[1]=bhi.y; bh[2]=bhi.z; bh[3]=bhi.w;
            }
        }

        #pragma unroll
        for (int s = 0; s < 2; ++s) {
            uint4 af[4]; uint2 bf[4];
            #pragma unroll
            for (int mt = 0; mt < 4; ++mt)
                af[mt] = *(const uint4*)(Asl + (((s*16 + wm*4 + mt)*32 + lane) * 16));
            #pragma unroll
            for (int nt = 0; nt < 4; ++nt)
                bf[nt] = *(const uint2*)(Bsl + (((s*16 + wn*4 + nt)*32 + lane) * 8));
            #pragma unroll
            for (int mt = 0; mt < 4; ++mt)
                #pragma unroll
                for (int nt = 0; nt < 4; ++nt)
                    mma_f16(acc[mt][nt], af[mt].x, af[mt].z, af[mt].y, af[mt].w,
                            bf[nt].x, bf[nt].y);
        }
    }

    #pragma unroll
    for (int mt = 0; mt < 4; ++mt) {
        int m = m0 + wm*64 + mt*16 + (lane >> 2);
        #pragma unroll
        for (int nt = 0; nt < 4; ++nt) {
            int n = n0 + wn*32 + nt*8 + 2*(lane & 3);
            if (n < NQ) {
                *(float2*)&Tm[(size_t)m*NQ + n]     = make_float2(acc[mt][nt][0], acc[mt][nt][1]);
                *(float2*)&Tm[(size_t)(m+8)*NQ + n] = make_float2(acc[mt][nt][2], acc[mt][nt][3]);
            }
        }
    }
}

// ------------- gather epilogue + cosine-window blend -> output (2,128,80,80)
__global__ void k_combine(float* __restrict__ out) {
    int idx = blockIdx.x*blockDim.x + threadIdx.x;
    const int total = NB*NC*FH*FW;
    if (idx >= total) return;
    int X = idx % FW; int t = idx / FW;
    int Y = t % FH; t /= FH;
    int c = t % NC; int b = t / NC;

    int dys[2], hh[2]; int ny = 0;
    if ((Y & 1) == 0) {
        dys[ny] = 0; hh[ny] = Y >> 1; ny++;
        if (Y >= 2) { dys[ny] = 2; hh[ny] = (Y-2) >> 1; ny++; }
    } else {
        dys[ny] = 1; hh[ny] = (Y-1) >> 1; ny++;
        if (Y <= 2*HS - 3) { dys[ny] = -1; hh[ny] = (Y+1) >> 1; ny++; }
    }
    int dxs[2], ww[2]; int nx = 0;
    if ((X & 1) == 0) {
        dxs[nx] = 0; ww[nx] = X >> 1; nx++;
        if (X >= 2) { dxs[nx] = 2; ww[nx] = (X-2) >> 1; nx++; }
    } else {
        dxs[nx] = 1; ww[nx] = (X-1) >> 1; nx++;
        if (X <= 2*HS - 3) { dxs[nx] = -1; ww[nx] = (X+1) >> 1; nx++; }
    }

    const float PI = 3.14159265358979323846f;
    float wl = 0.5f*(1.f + cosf(PI * (float)X        / (float)(FW-1)));
    float wr = 0.5f*(1.f + cosf(PI * (float)(FW-1-X) / (float)(FW-1)));

    float res = 0.f;
    for (int s = 0; s < 2; ++s) {
        const float* T = g_T + (size_t)(b*2 + s)*MROWS*NQ;
        float acc = 0.f;
        for (int iy = 0; iy < ny; ++iy) {
            for (int ix = 0; ix < nx; ++ix) {
                int m = c*16 + (dys[iy]+1)*4 + (dxs[ix]+1);
                acc += T[(size_t)m*NQ + hh[iy]*HS + ww[ix]];
            }
        }
        res += (s == 0 ? wl : wr) * 0.25f * acc;
    }
    out[idx] = res;
}

// ------------------------------------------------------------------ launcher
extern "C" void kernel_launch(void* const* d_in, const int* in_sizes, int n_in,
                              void* d_out, int out_size) {
    const float* left      = (const float*)d_in[0];
    const float* right     = (const float*)d_in[1];
    const float* mid       = (const float*)d_in[2];
    const float* raw_left  = (const float*)d_in[3];
    const float* raw_right = (const float*)d_in[4];
    float* outp = (float*)d_out;

    cudaFuncSetAttribute(k_gemm2h, cudaFuncAttributeMaxDynamicSharedMemorySize, G2_SMEM);

    int t1 = NB*3*NC*NQ;
    k_downsample<<<(t1+255)/256, 256>>>(left, right, mid);
    k_cvt<<<dim3(NQ/32, NC/32, NB*3), dim3(32, 8)>>>();
    int t2 = NB*2*NQ;
    k_sumsq<<<(t2+127)/128, 128>>>();
    k_norm<<<(t2+127)/128, 128>>>();

    dim3 g1((NQ+127)/128, (NQ+127)/128, NB*2);   // 13 x 13 x 4
    k_gemm1h<<<g1, 256>>>();

    k_psAB<<<NB*2*HS*HS, 256>>>();               // fused passes A+B

    int tC = NB*2*(NQ/4)*(NQ+4);
    k_passC<<<(tC+255)/256, 256>>>();

    int tD = NB*2*10*HS*(HS+3)*HS;
    k_passD<<<(tD+255)/256, 256>>>();

    k_softmax_stats<<<dim3(NQ/64, NB*2), 256>>>();
    k_attnT<<<dim3(NQ/32, NQ/32, NB*2), dim3(32, 8)>>>();

    int tg8 = NB*2*MROWS*(NQ/8);
    k_buildG<<<(tg8+255)/256, 256>>>(raw_left, raw_right);

    dim3 g2(MROWS/256, (NQ+127)/128, NB*2);      // 8 x 13 x 4
    k_gemm2h<<<g2, 512, G2_SMEM>>>();

    int to = NB*NC*FH*FW;
    k_combine<<<(to+255)/256, 256>>>(outp);
}